// round 15
// baseline (speedup 1.0000x reference)
#include <cuda_runtime.h>
#include <cuda_fp16.h>
#include <cstdint>
#include <math.h>

#define NB   1024
#define NC   119
#define ND   1024
#define NH   16
#define SEQ  64
#define MR   (NB*SEQ)     // 65536 rows
#define KPAD 128

// ---- mma.sync fallback GEMM tiling: CTA 128x128, BK=32 halves -----------------
#define PADKA 20
#define PADKB 24
#define ASTG  (128 * PADKA)
#define BSTG  (128 * PADKB)
#define NSTG  4
#define GSMEM ((ASTG + BSTG) * NSTG * 4)   // 90112 bytes

// ---- tcgen05 GEMM: CTA 256(M) x 256(N), K64 chunks, 3-stage ring --------------
#define TC_A_OFF  1024u
#define TC_ASTG   32768u                     // 256 rows x 128B
#define TC_B_OFF  (1024u + 3u * 32768u)      // 99328
#define TC_BSTG   32768u
#define TC_SMEM   (TC_B_OFF + 3u * 32768u)   // 197632 bytes

// ---------------- scratch ----------------------------------------------------
__device__ __half g_xin [(size_t)MR * KPAD];
__device__ __half g_Wt  [(size_t)3 * ND * ND];   // transposed fp16 weights (natural K)
__device__ float  g_bqkv[3 * ND];
__device__ __half g_xh  [(size_t)MR * ND];       // fp16 x (embed out, residual)
__device__ __half g_qkvh[(size_t)MR * 3 * ND];   // fp16 qkv
__device__ __half g_o   [(size_t)MR * ND];
__device__ __half g_yh  [(size_t)MR * ND];       // fp16 pre-LN y

// ---------------- helpers -----------------------------------------------------
__device__ __forceinline__ uint32_t smem_u32(const void* p) {
    uint32_t a;
    asm("{ .reg .u64 t; cvta.to.shared.u64 t, %1; cvt.u32.u64 %0, t; }" : "=r"(a) : "l"(p));
    return a;
}
__device__ __forceinline__ void cp_async16(uint32_t saddr, const void* gptr) {
    asm volatile("cp.async.cg.shared.global [%0], [%1], 16;" :: "r"(saddr), "l"(gptr));
}
#define CP_COMMIT() asm volatile("cp.async.commit_group;")
#define CP_WAIT(n)  asm volatile("cp.async.wait_group %0;" :: "n"(n))

#define MBAR_WAIT(mb, par) do {                                              \
    uint32_t _d;                                                             \
    asm volatile("{\n\t.reg .pred p;\n\t"                                    \
        "mbarrier.try_wait.parity.acquire.cta.shared::cta.b64 p, [%1], %2;\n\t" \
        "selp.b32 %0, 1, 0, p;\n\t}" : "=r"(_d) : "r"(mb), "r"(par) : "memory"); \
    if (!_d) {                                                               \
        asm volatile("{\n\t.reg .pred P1;\n\t"                               \
            "W_%=:\n\t"                                                      \
            "mbarrier.try_wait.parity.acquire.cta.shared::cta.b64 P1, [%0], %1, 0x989680;\n\t" \
            "@P1 bra.uni D_%=;\n\t"                                          \
            "bra.uni W_%=;\n\t"                                              \
            "D_%=:\n\t}" :: "r"(mb), "r"(par) : "memory");                   \
    }                                                                        \
} while (0)

__device__ __forceinline__ uint32_t h2_as_u32(__half2 v) {
    return *reinterpret_cast<uint32_t*>(&v);
}

// m16n8k16 fp16 mma, fp32 accumulate (fallback + attention)
__device__ __forceinline__ void mma_f16(float* d, const uint32_t* a, const uint32_t* b) {
    asm volatile("mma.sync.aligned.m16n8k16.row.col.f32.f16.f16.f32 "
        "{%0,%1,%2,%3}, {%4,%5,%6,%7}, {%8,%9}, {%0,%1,%2,%3};"
        : "+f"(d[0]), "+f"(d[1]), "+f"(d[2]), "+f"(d[3])
        : "r"(a[0]), "r"(a[1]), "r"(a[2]), "r"(a[3]), "r"(b[0]), "r"(b[1]));
}

// ---------------- board (B,C,8,8) -> xin (B*64, KPAD) fp16 --------------------
__global__ void board_transpose_kernel(const float* __restrict__ board) {
    __shared__ float tile[NC * 65];
    int b = blockIdx.x;
    const float* src = board + (size_t)b * NC * SEQ;
    for (int i = threadIdx.x; i < NC * SEQ; i += blockDim.x) {
        int c = i >> 6, s = i & 63;
        tile[c * 65 + s] = src[i];
    }
    __syncthreads();
    __half* dst = g_xin + (size_t)b * SEQ * KPAD;
    for (int i = threadIdx.x; i < SEQ * KPAD; i += blockDim.x) {
        int s = i >> 7, c = i & 127;
        dst[i] = (c < NC) ? __float2half(tile[c * 65 + s]) : __float2half(0.f);
    }
}

// ---- weight transpose W(R x Cw) -> Wt(Cw x Rpad) fp16, natural K order -------
__global__ void transpose_kernel(const float* __restrict__ W, __half* __restrict__ Wt,
                                 int R, int Cw, int Rpad) {
    __shared__ float t[32][33];
    int bx = blockIdx.x * 32;
    int by = blockIdx.y * 32;
    int tx = threadIdx.x, ty = threadIdx.y;
    #pragma unroll
    for (int i = 0; i < 4; i++) {
        int r = by + ty + i * 8, c = bx + tx;
        t[ty + i * 8][tx] = (r < R) ? W[(size_t)r * Cw + c] : 0.f;
    }
    __syncthreads();
    #pragma unroll
    for (int i = 0; i < 4; i++) {
        int c = bx + ty + i * 8;   // n (output row)
        int k = by + tx;           // k (natural order)
        Wt[(size_t)c * Rpad + k] = __float2half(t[tx][ty + i * 8]);
    }
}

__global__ void concat_bias_kernel(const float* __restrict__ bq,
                                   const float* __restrict__ bk,
                                   const float* __restrict__ bv) {
    int i = blockIdx.x * blockDim.x + threadIdx.x;
    if (i >= 3 * ND) return;
    g_bqkv[i] = (i < ND) ? bq[i] : (i < 2 * ND) ? bk[i - ND] : bv[i - 2 * ND];
}

// ---------------- fallback fp16 mma.sync GEMM ----------------------------------
__global__ __launch_bounds__(256, 2)
void gemm_mma_kernel(const __half* __restrict__ A, const __half* __restrict__ Bt,
                     const float* __restrict__ bias,
                     const __half* __restrict__ resh, const float* __restrict__ pos,
                     __half* __restrict__ Ch, int K, int ldc)
{
    extern __shared__ uint32_t dynsm[];
    uint32_t* As = dynsm;
    uint32_t* Bs = dynsm + NSTG * ASTG;

    const int tid = threadIdx.x;
    const int lane = tid & 31, wid = tid >> 5;
    const int g = lane >> 2, t = lane & 3;
    const int wm = wid >> 2, wn = wid & 3;
    const int bm = blockIdx.y * 128, bn = blockIdx.x * 128;

    const int lrow = tid >> 1, seg = tid & 1;
    const __half* pA = A  + (size_t)(bm + lrow) * K + seg * 16;
    const __half* pB = Bt + (size_t)(bn + lrow) * K + seg * 16;
    uint32_t aOff[2], bOff[2];
    {
        const uint32_t aBase = smem_u32(As), bBase = smem_u32(Bs);
        #pragma unroll
        for (int q = 0; q < 2; q++) {
            aOff[q] = aBase + (uint32_t)(lrow * PADKA + seg * 8 + q * 4) * 4;
            bOff[q] = bBase + (uint32_t)(lrow * PADKB + seg * 8 + q * 4) * 4;
        }
    }

    const int nk = K / 32;

    float acc[4][4][4];
    #pragma unroll
    for (int i = 0; i < 4; i++)
        #pragma unroll
        for (int j = 0; j < 4; j++)
            #pragma unroll
            for (int r = 0; r < 4; r++) acc[i][j][r] = 0.f;

    #pragma unroll
    for (int st = 0; st < 3; st++) {
        const uint32_t soa = (uint32_t)st * (ASTG * 4);
        const uint32_t sob = (uint32_t)st * (BSTG * 4);
        const int k0 = st * 32;
        #pragma unroll
        for (int q = 0; q < 2; q++) {
            cp_async16(aOff[q] + soa, pA + k0 + q * 8);
            cp_async16(bOff[q] + sob, pB + k0 + q * 8);
        }
        CP_COMMIT();
    }

    for (int it = 0; it < nk; it++) {
        const int s = it & 3;
        const int rem = nk - 1 - it;
        if (rem >= 2)      { CP_WAIT(2); }
        else if (rem == 1) { CP_WAIT(1); }
        else               { CP_WAIT(0); }
        __syncthreads();

        if (it + 3 < nk) {
            const int s2 = (it + 3) & 3;
            const uint32_t soa = (uint32_t)s2 * (ASTG * 4);
            const uint32_t sob = (uint32_t)s2 * (BSTG * 4);
            const int k0 = (it + 3) * 32;
            #pragma unroll
            for (int q = 0; q < 2; q++) {
                cp_async16(aOff[q] + soa, pA + k0 + q * 8);
                cp_async16(bOff[q] + sob, pB + k0 + q * 8);
            }
            CP_COMMIT();
        }

        const uint32_t* Ab = As + s * ASTG;
        const uint32_t* Bb = Bs + s * BSTG;
        #pragma unroll
        for (int gk = 0; gk < 2; gk++) {
            const int kb = gk * 8;
            uint32_t a[4][4];
            uint32_t b[4][2];
            #pragma unroll
            for (int i = 0; i < 4; i++) {
                int r = (wm * 64 + i * 16 + g) * PADKA + kb + t;
                a[i][0] = Ab[r];
                a[i][1] = Ab[r + 8 * PADKA];
                a[i][2] = Ab[r + 4];
                a[i][3] = Ab[r + 8 * PADKA + 4];
            }
            #pragma unroll
            for (int j = 0; j < 4; j++) {
                int c = (wn * 32 + j * 8 + g) * PADKB + kb + t;
                b[j][0] = Bb[c];
                b[j][1] = Bb[c + 4];
            }
            #pragma unroll
            for (int i = 0; i < 4; i++)
                #pragma unroll
                for (int j = 0; j < 4; j++)
                    mma_f16(acc[i][j], a[i], b[j]);
        }
    }

    #pragma unroll
    for (int i = 0; i < 4; i++) {
        int r0 = bm + wm * 64 + i * 16 + g;
        #pragma unroll
        for (int j = 0; j < 4; j++) {
            int cg = bn + wn * 32 + j * 8 + t * 2;
            float2 b2 = *(const float2*)&bias[cg];
            float o00 = acc[i][j][0] + b2.x, o01 = acc[i][j][1] + b2.y;
            float o10 = acc[i][j][2] + b2.x, o11 = acc[i][j][3] + b2.y;
            size_t row0 = (size_t)r0 * ldc + cg;
            size_t row1 = (size_t)(r0 + 8) * ldc + cg;
            if (resh) {
                __half2 x0 = *(const __half2*)&resh[row0];
                __half2 x1 = *(const __half2*)&resh[row1];
                o00 += __half2float(x0.x); o01 += __half2float(x0.y);
                o10 += __half2float(x1.x); o11 += __half2float(x1.y);
            }
            if (pos) {
                float2 p0 = *(const float2*)&pos[(size_t)(r0 & 63) * ND + cg];
                float2 p1 = *(const float2*)&pos[(size_t)((r0 + 8) & 63) * ND + cg];
                o00 += p0.x; o01 += p0.y; o10 += p1.x; o11 += p1.y;
            }
            *(__half2*)&Ch[row0] = __floats2half2_rn(o00, o01);
            *(__half2*)&Ch[row1] = __floats2half2_rn(o10, o11);
        }
    }
}

// ---------------- tcgen05 SS f16 GEMM (sm_103a arch-specific path) ------------
// CTA 256(M) x 256(N); K64 chunks; 3-stage ring; D in TMEM (2 x 256 cols fp32).
__global__ __launch_bounds__(256, 1)
void gemm_tc_kernel(const __half* __restrict__ A, const __half* __restrict__ Bt,
                    const float* __restrict__ bias,
                    const __half* __restrict__ resh, const float* __restrict__ pos,
                    __half* __restrict__ Ch, int K, int ldc)
{
#if defined(__CUDA_ARCH_SPECIFIC__) && (__CUDA_ARCH__ >= 1000)
    extern __shared__ char smem[];
    const uint32_t sb = smem_u32(smem);
    const int tid = threadIdx.x, lane = tid & 31, wid = tid >> 5;
    const int bm = blockIdx.y * 256, bn = blockIdx.x * 256;

    if (wid == 0) {
        asm volatile("tcgen05.alloc.cta_group::1.sync.aligned.shared::cta.b32 [%0], %1;"
                     :: "r"(sb), "r"(512u) : "memory");
    }
    if (tid == 0) {
        #pragma unroll
        for (int s = 0; s < 3; s++)
            asm volatile("mbarrier.init.shared.b64 [%0], %1;"
                         :: "r"(sb + 8 + 8 * s), "r"(1u) : "memory");
    }
    __syncthreads();
    uint32_t tmem;
    asm volatile("ld.shared.b32 %0, [%1];" : "=r"(tmem) : "r"(sb));

    // loaders: thread tid -> A row tid and B row tid (256 rows each), 8 granules
    const int lr = tid;
    const __half* pA = A  + (size_t)(bm + lr) * K;
    const __half* pB = Bt + (size_t)(bn + lr) * K;
    uint32_t aDst[8], bDst[8];
    #pragma unroll
    for (int q = 0; q < 8; q++) {
        int sw = (q ^ (lr & 7)) * 16;
        aDst[q] = sb + TC_A_OFF + (uint32_t)lr * 128 + sw;
        bDst[q] = sb + TC_B_OFF + (uint32_t)lr * 128 + sw;
    }

    const int nk = K / 64;
    const uint32_t idesc = (1u << 4) | ((256u / 8u) << 17) | ((128u / 16u) << 24);
    const uint64_t DESC_BASE =
        (uint64_t(2) << 61) | (uint64_t(1) << 46) | (uint64_t(64) << 32) | (uint64_t(1) << 16);

    // prologue: fill chunks 0..1 (stages 0..1)
    #pragma unroll
    for (int st = 0; st < 2; st++) {
        if (st < nk) {
            const int k0 = st * 64;
            #pragma unroll
            for (int q = 0; q < 8; q++) {
                cp_async16(aDst[q] + st * TC_ASTG, pA + k0 + q * 8);
                cp_async16(bDst[q] + st * TC_BSTG, pB + k0 + q * 8);
            }
            CP_COMMIT();
        }
    }

    uint32_t ph0 = 0, ph1 = 0, ph2 = 0;   // per-stage mbar phase
    int stage = 0;                        // stage of chunk `it` (it % 3)
    for (int it = 0; it < nk; it++) {
        if (it + 1 < nk) { CP_WAIT(1); } else { CP_WAIT(0); }
        __syncthreads();   // stage `stage` (chunk it) fully resident

        // issue 8 MMAs for chunk it (two M-halves), commit to mbar[stage]
        if (wid == 0) {
            uint32_t pr;
            asm volatile("{\n\t.reg .pred p;\n\telect.sync _|p, 0xFFFFFFFF;\n\t"
                         "selp.b32 %0, 1, 0, p;\n\t}" : "=r"(pr));
            if (pr) {
                uint64_t ad = DESC_BASE | (((uint64_t)((sb + TC_A_OFF + stage * TC_ASTG) >> 4)) & 0x3FFF);
                uint64_t bd = DESC_BASE | (((uint64_t)((sb + TC_B_OFF + stage * TC_BSTG) >> 4)) & 0x3FFF);
                #pragma unroll
                for (int s = 0; s < 4; s++) {
                    uint32_t en = ((it > 0) || (s > 0)) ? 1u : 0u;
                    asm volatile("{\n\t.reg .pred p;\n\tsetp.ne.u32 p, %5, 0;\n\t"
                        "tcgen05.mma.cta_group::1.kind::f16 [%0], %1, %2, %3, {%4, %4, %4, %4}, p;\n\t}"
                        :: "r"(tmem), "l"(ad + 2 * s), "l"(bd + 2 * s), "r"(idesc),
                           "r"(0u), "r"(en) : "memory");
                    asm volatile("{\n\t.reg .pred p;\n\tsetp.ne.u32 p, %5, 0;\n\t"
                        "tcgen05.mma.cta_group::1.kind::f16 [%0], %1, %2, %3, {%4, %4, %4, %4}, p;\n\t}"
                        :: "r"(tmem + 256), "l"(ad + 1024 + 2 * s), "l"(bd + 2 * s), "r"(idesc),
                           "r"(0u), "r"(en) : "memory");
                }
                asm volatile(
                    "tcgen05.commit.cta_group::1.mbarrier::arrive::one.shared::cluster.b64 [%0];"
                    :: "r"(sb + 8 + (uint32_t)stage * 8) : "memory");
            }
        }

        // refill stage for chunk it+2 (previous user: chunk it-1, same stage)
        if (it + 2 < nk) {
            const int s2 = (stage + 2 >= 3) ? (stage - 1) : (stage + 2);   // (it+2)%3
            if (it >= 1) {
                const uint32_t mb = sb + 8 + (uint32_t)s2 * 8;
                uint32_t par = (s2 == 0) ? ph0 : (s2 == 1) ? ph1 : ph2;
                MBAR_WAIT(mb, par);
                if (s2 == 0) ph0 ^= 1; else if (s2 == 1) ph1 ^= 1; else ph2 ^= 1;
            }
            const int k0 = (it + 2) * 64;
            #pragma unroll
            for (int q = 0; q < 8; q++) {
                cp_async16(aDst[q] + s2 * TC_ASTG, pA + k0 + q * 8);
                cp_async16(bDst[q] + s2 * TC_BSTG, pB + k0 + q * 8);
            }
            CP_COMMIT();
        }

        stage = (stage + 1 == 3) ? 0 : stage + 1;
    }

    // final wait: commit of chunk nk-1 (serial queue covers all prior MMAs)
    {
        const int sl = (nk - 1) % 3;
        const uint32_t mb = sb + 8 + (uint32_t)sl * 8;
        uint32_t par = (sl == 0) ? ph0 : (sl == 1) ? ph1 : ph2;
        MBAR_WAIT(mb, par);
    }
    asm volatile("tcgen05.fence::after_thread_sync;" ::: "memory");

    // epilogue: warp w -> M-half (w>>2), rows (w&3)*32+lane; 8 col-chunks of 32
    const int sub = wid & 3, half = wid >> 2;
    const int rg = bm + half * 128 + sub * 32 + lane;
    const uint32_t tbase = tmem + (uint32_t)half * 256;
    #pragma unroll
    for (int c = 0; c < 8; c++) {
        const int c0 = c * 32;
        uint32_t dr[32];
        asm volatile("tcgen05.ld.sync.aligned.32x32b.x32.b32 "
            "{%0, %1, %2, %3, %4, %5, %6, %7, %8, %9, %10, %11, %12, %13, %14, %15, "
            " %16, %17, %18, %19, %20, %21, %22, %23, %24, %25, %26, %27, %28, %29, %30, %31}, [%32];"
            : "=r"(dr[0]),  "=r"(dr[1]),  "=r"(dr[2]),  "=r"(dr[3]),
              "=r"(dr[4]),  "=r"(dr[5]),  "=r"(dr[6]),  "=r"(dr[7]),
              "=r"(dr[8]),  "=r"(dr[9]),  "=r"(dr[10]), "=r"(dr[11]),
              "=r"(dr[12]), "=r"(dr[13]), "=r"(dr[14]), "=r"(dr[15]),
              "=r"(dr[16]), "=r"(dr[17]), "=r"(dr[18]), "=r"(dr[19]),
              "=r"(dr[20]), "=r"(dr[21]), "=r"(dr[22]), "=r"(dr[23]),
              "=r"(dr[24]), "=r"(dr[25]), "=r"(dr[26]), "=r"(dr[27]),
              "=r"(dr[28]), "=r"(dr[29]), "=r"(dr[30]), "=r"(dr[31])
            : "r"(tbase + c0));
        asm volatile("tcgen05.wait::ld.sync.aligned;" ::: "memory");

        const int cb = bn + c0;
        const size_t rowoff = (size_t)rg * ldc + cb;
        float v[32];
        #pragma unroll
        for (int q = 0; q < 8; q++) {
            float4 b4 = *(const float4*)&bias[cb + q * 4];
            v[q*4+0] = __uint_as_float(dr[q*4+0]) + b4.x;
            v[q*4+1] = __uint_as_float(dr[q*4+1]) + b4.y;
            v[q*4+2] = __uint_as_float(dr[q*4+2]) + b4.z;
            v[q*4+3] = __uint_as_float(dr[q*4+3]) + b4.w;
        }
        if (resh) {
            #pragma unroll
            for (int q = 0; q < 4; q++) {
                uint4 rh = *(const uint4*)&resh[rowoff + q * 8];
                const __half2* hp = (const __half2*)&rh;
                #pragma unroll
                for (int e = 0; e < 4; e++) {
                    float2 f = __half22float2(hp[e]);
                    v[q * 8 + e * 2]     += f.x;
                    v[q * 8 + e * 2 + 1] += f.y;
                }
            }
        }
        if (pos) {
            const float* pp = pos + (size_t)(rg & 63) * ND + cb;
            #pragma unroll
            for (int j = 0; j < 32; j += 4) {
                float4 p4 = *(const float4*)&pp[j];
                v[j] += p4.x; v[j+1] += p4.y; v[j+2] += p4.z; v[j+3] += p4.w;
            }
        }
        #pragma unroll
        for (int q = 0; q < 4; q++) {
            __half2 h[4];
            #pragma unroll
            for (int e = 0; e < 4; e++)
                h[e] = __floats2half2_rn(v[q * 8 + e * 2], v[q * 8 + e * 2 + 1]);
            *(uint4*)&Ch[rowoff + q * 8] = *(uint4*)h;
        }
    }

    asm volatile("tcgen05.fence::before_thread_sync;" ::: "memory");
    __syncthreads();
    if (tid == 0) {
        #pragma unroll
        for (int s = 0; s < 3; s++)
            asm volatile("mbarrier.inval.shared.b64 [%0];" :: "r"(sb + 8 + 8 * s) : "memory");
    }
    __syncthreads();
    if (wid == 0) {
        asm volatile("tcgen05.dealloc.cta_group::1.sync.aligned.b32 %0, %1;" :: "r"(tmem), "r"(512u));
    }
#endif
}

// ---------------- attention: fp16 MMA flash kernel, one (b,h) per block -------
#define TPITCH 36

__global__ __launch_bounds__(128)
void attn_kernel(const float* __restrict__ rel_bias)
{
    __shared__ uint32_t qs[64 * TPITCH];
    __shared__ uint32_t ks[64 * TPITCH];
    __shared__ uint32_t vs[64 * TPITCH];

    const int h = blockIdx.x, b = blockIdx.y;
    const int tid = threadIdx.x;
    const int lane = tid & 31, w = tid >> 5;
    const int g = lane >> 2, t = lane & 3;

    const __half* qbase = g_qkvh + (size_t)b * SEQ * (3 * ND) + h * 64;

    __half* vsH = (__half*)vs;
    for (int idx = tid; idx < 512; idx += 128) {
        int s = idx >> 3, dg = idx & 7;
        const size_t r = (size_t)s * (3 * ND) + dg * 8;
        uint4 vq = *(const uint4*)(qbase + r);
        uint4 vk = *(const uint4*)(qbase + r + ND);
        *(uint4*)&qs[s * TPITCH + dg * 4] = vq;
        *(uint4*)&ks[s * TPITCH + dg * 4] = vk;
        uint4 vv = *(const uint4*)(qbase + r + 2 * ND);
        __half hv[8];
        *(uint4*)hv = vv;
        #pragma unroll
        for (int q = 0; q < 8; q++)
            vsH[(dg * 8 + q) * (TPITCH * 2) + s] = hv[q];
    }
    __syncthreads();

    float sc[8][4];
    #pragma unroll
    for (int j = 0; j < 8; j++)
        #pragma unroll
        for (int r = 0; r < 4; r++) sc[j][r] = 0.f;

    const int arow0 = (w * 16 + g) * TPITCH;
    const int arow1 = (w * 16 + g + 8) * TPITCH;
    #pragma unroll
    for (int kt = 0; kt < 4; kt++) {
        uint32_t a[4];
        a[0] = qs[arow0 + kt * 8 + t];
        a[1] = qs[arow1 + kt * 8 + t];
        a[2] = qs[arow0 + kt * 8 + t + 4];
        a[3] = qs[arow1 + kt * 8 + t + 4];
        #pragma unroll
        for (int j = 0; j < 8; j++) {
            uint32_t bf[2];
            int br = (j * 8 + g) * TPITCH + kt * 8 + t;
            bf[0] = ks[br];
            bf[1] = ks[br + 4];
            mma_f16(sc[j], a, bf);
        }
    }

    const float* rb = rel_bias + (size_t)h * 4096 + (size_t)(w * 16 + g) * 64;
    #pragma unroll
    for (int j = 0; j < 8; j++) {
        float2 b0 = *(const float2*)&rb[j * 8 + 2 * t];
        float2 b1 = *(const float2*)&rb[8 * 64 + j * 8 + 2 * t];
        sc[j][0] = sc[j][0] * 0.125f + b0.x;
        sc[j][1] = sc[j][1] * 0.125f + b0.y;
        sc[j][2] = sc[j][2] * 0.125f + b1.x;
        sc[j][3] = sc[j][3] * 0.125f + b1.y;
    }

    float m0 = -1e30f, m1 = -1e30f;
    #pragma unroll
    for (int j = 0; j < 8; j++) {
        m0 = fmaxf(m0, fmaxf(sc[j][0], sc[j][1]));
        m1 = fmaxf(m1, fmaxf(sc[j][2], sc[j][3]));
    }
    m0 = fmaxf(m0, __shfl_xor_sync(0xffffffffu, m0, 1));
    m0 = fmaxf(m0, __shfl_xor_sync(0xffffffffu, m0, 2));
    m1 = fmaxf(m1, __shfl_xor_sync(0xffffffffu, m1, 1));
    m1 = fmaxf(m1, __shfl_xor_sync(0xffffffffu, m1, 2));
    float s0 = 0.f, s1 = 0.f;
    #pragma unroll
    for (int j = 0; j < 8; j++) {
        sc[j][0] = __expf(sc[j][0] - m0); s0 += sc[j][0];
        sc[j][1] = __expf(sc[j][1] - m0); s0 += sc[j][1];
        sc[j][2] = __expf(sc[j][2] - m1); s1 += sc[j][2];
        sc[j][3] = __expf(sc[j][3] - m1); s1 += sc[j][3];
    }
    s0 += __shfl_xor_sync(0xffffffffu, s0, 1);
    s0 += __shfl_xor_sync(0xffffffffu, s0, 2);
    s1 += __shfl_xor_sync(0xffffffffu, s1, 1);
    s1 += __shfl_xor_sync(0xffffffffu, s1, 2);
    const float inv0 = 1.f / s0, inv1 = 1.f / s1;

    uint32_t pa[4][4];
    #pragma unroll
    for (int kt = 0; kt < 4; kt++) {
        pa[kt][0] = h2_as_u32(__floats2half2_rn(sc[2*kt][0]   * inv0, sc[2*kt][1]   * inv0));
        pa[kt][1] = h2_as_u32(__floats2half2_rn(sc[2*kt][2]   * inv1, sc[2*kt][3]   * inv1));
        pa[kt][2] = h2_as_u32(__floats2half2_rn(sc[2*kt+1][0] * inv0, sc[2*kt+1][1] * inv0));
        pa[kt][3] = h2_as_u32(__floats2half2_rn(sc[2*kt+1][2] * inv1, sc[2*kt+1][3] * inv1));
    }

    float oc[8][4];
    #pragma unroll
    for (int j = 0; j < 8; j++)
        #pragma unroll
        for (int r = 0; r < 4; r++) oc[j][r] = 0.f;

    #pragma unroll
    for (int kt = 0; kt < 4; kt++) {
        #pragma unroll
        for (int j = 0; j < 8; j++) {
            uint32_t bf[2];
            int br = (j * 8 + g) * TPITCH + kt * 8 + t;
            bf[0] = vs[br];
            bf[1] = vs[br + 4];
            mma_f16(oc[j], pa[kt], bf);
        }
    }

    __half* ob0 = g_o + (size_t)(b * SEQ + w * 16 + g) * ND + h * 64;
    __half* ob1 = ob0 + (size_t)8 * ND;
    #pragma unroll
    for (int j = 0; j < 8; j++) {
        *(__half2*)&ob0[j * 8 + 2 * t] = __floats2half2_rn(oc[j][0], oc[j][1]);
        *(__half2*)&ob1[j * 8 + 2 * t] = __floats2half2_rn(oc[j][2], oc[j][3]);
    }
}

// ---------------- LayerNorm: warp-per-row (fp16 in, fp32 out) -----------------
__global__ __launch_bounds__(256)
void ln_kernel(const float* __restrict__ gamma, const float* __restrict__ beta,
               float* __restrict__ out)
{
    const int wid = threadIdx.x >> 5, lane = threadIdx.x & 31;
    const size_t row = ((size_t)blockIdx.x * 8 + wid) * ND;
    const int base = lane * 32;

    float v[32];
    #pragma unroll
    for (int q = 0; q < 4; q++) {
        uint4 raw = *(const uint4*)&g_yh[row + base + q * 8];
        const __half2* hp = (const __half2*)&raw;
        #pragma unroll
        for (int e = 0; e < 4; e++) {
            float2 f = __half22float2(hp[e]);
            v[q * 8 + e * 2]     = f.x;
            v[q * 8 + e * 2 + 1] = f.y;
        }
    }

    float s = 0.f;
    #pragma unroll
    for (int j = 0; j < 32; j++) s += v[j];
    #pragma unroll
    for (int o = 16; o > 0; o >>= 1) s += __shfl_xor_sync(0xffffffffu, s, o);
    const float mu = s * (1.f / ND);

    float sq = 0.f;
    #pragma unroll
    for (int j = 0; j < 32; j++) { v[j] -= mu; sq += v[j] * v[j]; }
    #pragma unroll
    for (int o = 16; o > 0; o >>= 1) sq += __shfl_xor_sync(0xffffffffu, sq, o);
    const float inv = rsqrtf(sq * (1.f / ND) + 1e-5f);

    #pragma unroll
    for (int q = 0; q < 8; q++) {
        float4 g4 = *(const float4*)&gamma[base + q * 4];
        float4 b4 = *(const float4*)&beta[base + q * 4];
        float4 o4;
        o4.x = v[q*4+0] * inv * g4.x + b4.x;
        o4.y = v[q*4+1] * inv * g4.y + b4.y;
        o4.z = v[q*4+2] * inv * g4.z + b4.z;
        o4.w = v[q*4+3] * inv * g4.w + b4.w;
        *(float4*)&out[row + base + q * 4] = o4;
    }
}

// ---------------- launch -------------------------------------------------------
extern "C" void kernel_launch(void* const* d_in, const int* in_sizes, int n_in,
                              void* d_out, int out_size)
{
    const float* board = (const float*)d_in[0];
    const float* embW  = (const float*)d_in[1];
    const float* embB  = (const float*)d_in[2];
    const float* pos   = (const float*)d_in[3];
    const float* Wq    = (const float*)d_in[4];
    const float* bq    = (const float*)d_in[5];
    const float* Wk    = (const float*)d_in[6];
    const float* bk    = (const float*)d_in[7];
    const float* Wv    = (const float*)d_in[8];
    const float* bv    = (const float*)d_in[9];
    const float* Wo    = (const float*)d_in[10];
    const float* bo    = (const float*)d_in[11];
    const float* relb  = (const float*)d_in[12];
    const float* lng   = (const float*)d_in[13];
    const float* lnb   = (const float*)d_in[14];
    float* out = (float*)d_out;

    __half *xin, *wt, *xh, *qkvh, *o, *yh;
    float *bqkv;
    cudaGetSymbolAddress((void**)&xin,  g_xin);
    cudaGetSymbolAddress((void**)&wt,   g_Wt);
    cudaGetSymbolAddress((void**)&bqkv, g_bqkv);
    cudaGetSymbolAddress((void**)&xh,   g_xh);
    cudaGetSymbolAddress((void**)&qkvh, g_qkvh);
    cudaGetSymbolAddress((void**)&o,    g_o);
    cudaGetSymbolAddress((void**)&yh,   g_yh);

    cudaFuncSetAttribute(gemm_mma_kernel,
                         cudaFuncAttributeMaxDynamicSharedMemorySize, GSMEM);
    cudaFuncSetAttribute(gemm_tc_kernel,
                         cudaFuncAttributeMaxDynamicSharedMemorySize, TC_SMEM);

    // Runtime dispatch: tcgen05 body exists only in the sm_103a cubin.
    cudaFuncAttributes fa{};
    cudaFuncGetAttributes(&fa, gemm_tc_kernel);
    const bool use_tc = (fa.numRegs >= 32);

    board_transpose_kernel<<<NB, 256>>>(board);
    concat_bias_kernel<<<(3 * ND + 255) / 256, 256>>>(bq, bk, bv);

    dim3 tb(32, 8);

    transpose_kernel<<<dim3(ND / 32, KPAD / 32), tb>>>(embW, wt, NC, ND, KPAD);
    if (use_tc)
        gemm_tc_kernel<<<dim3(ND / 256, MR / 256), 256, TC_SMEM>>>(
            xin, wt, embB, nullptr, pos, xh, KPAD, ND);
    else
        gemm_mma_kernel<<<dim3(ND / 128, MR / 128), 256, GSMEM>>>(
            xin, wt, embB, nullptr, pos, xh, KPAD, ND);

    transpose_kernel<<<dim3(ND / 32, ND / 32), tb>>>(Wq, wt,                 ND, ND, ND);
    transpose_kernel<<<dim3(ND / 32, ND / 32), tb>>>(Wk, wt + (size_t)ND*ND,   ND, ND, ND);
    transpose_kernel<<<dim3(ND / 32, ND / 32), tb>>>(Wv, wt + (size_t)2*ND*ND, ND, ND, ND);
    if (use_tc)
        gemm_tc_kernel<<<dim3(3 * ND / 256, MR / 256), 256, TC_SMEM>>>(
            xh, wt, bqkv, nullptr, nullptr, qkvh, ND, 3 * ND);
    else
        gemm_mma_kernel<<<dim3(3 * ND / 128, MR / 128), 256, GSMEM>>>(
            xh, wt, bqkv, nullptr, nullptr, qkvh, ND, 3 * ND);

    attn_kernel<<<dim3(NH, NB), 128>>>(relb);

    transpose_kernel<<<dim3(ND / 32, ND / 32), tb>>>(Wo, wt, ND, ND, ND);
    if (use_tc)
        gemm_tc_kernel<<<dim3(ND / 256, MR / 256), 256, TC_SMEM>>>(
            o, wt, bo, xh, nullptr, yh, ND, ND);
    else
        gemm_mma_kernel<<<dim3(ND / 128, MR / 128), 256, GSMEM>>>(
            o, wt, bo, xh, nullptr, yh, ND, ND);

    ln_kernel<<<MR / 8, 256>>>(lng, lnb, out);
}

// round 16
// speedup vs baseline: 1.1500x; 1.1500x over previous
#include <cuda_runtime.h>
#include <cuda_fp16.h>
#include <cstdint>
#include <math.h>

#define NB   1024
#define NC   119
#define ND   1024
#define NH   16
#define SEQ  64
#define MR   (NB*SEQ)     // 65536 rows
#define KPAD 128

// ---- mma.sync fallback GEMM tiling: CTA 128x128, BK=32 halves -----------------
#define PADKA 20
#define PADKB 24
#define ASTG  (128 * PADKA)
#define BSTG  (128 * PADKB)
#define NSTG  4
#define GSMEM ((ASTG + BSTG) * NSTG * 4)   // 90112 bytes

// ---- tcgen05 GEMM: CTA 128(M) x 256(N), K64 chunks, 2-stage, 2 CTA/SM ---------
#define TC_A_OFF  1024u
#define TC_ASTG   16384u
#define TC_B_OFF  (1024u + 2u * 16384u)     // 33792
#define TC_BSTG   32768u
#define TC_SMEM   (TC_B_OFF + 2u * 32768u)  // 99328 bytes

// ---------------- scratch ----------------------------------------------------
__device__ __half g_xin [(size_t)MR * KPAD];
__device__ __half g_Wt  [(size_t)3 * ND * ND];   // transposed fp16 weights (natural K)
__device__ float  g_bqkv[3 * ND];
__device__ __half g_xh  [(size_t)MR * ND];       // fp16 x (embed out, residual)
__device__ __half g_qkvh[(size_t)MR * 3 * ND];   // fp16 qkv
__device__ __half g_o   [(size_t)MR * ND];
__device__ __half g_yh  [(size_t)MR * ND];       // fp16 pre-LN y

// ---------------- helpers -----------------------------------------------------
__device__ __forceinline__ uint32_t smem_u32(const void* p) {
    uint32_t a;
    asm("{ .reg .u64 t; cvta.to.shared.u64 t, %1; cvt.u32.u64 %0, t; }" : "=r"(a) : "l"(p));
    return a;
}
__device__ __forceinline__ void cp_async16(uint32_t saddr, const void* gptr) {
    asm volatile("cp.async.cg.shared.global [%0], [%1], 16;" :: "r"(saddr), "l"(gptr));
}
#define CP_COMMIT() asm volatile("cp.async.commit_group;")
#define CP_WAIT(n)  asm volatile("cp.async.wait_group %0;" :: "n"(n))

#define MBAR_WAIT(mb, par) do {                                              \
    uint32_t _d;                                                             \
    asm volatile("{\n\t.reg .pred p;\n\t"                                    \
        "mbarrier.try_wait.parity.acquire.cta.shared::cta.b64 p, [%1], %2;\n\t" \
        "selp.b32 %0, 1, 0, p;\n\t}" : "=r"(_d) : "r"(mb), "r"(par) : "memory"); \
    if (!_d) {                                                               \
        asm volatile("{\n\t.reg .pred P1;\n\t"                               \
            "W_%=:\n\t"                                                      \
            "mbarrier.try_wait.parity.acquire.cta.shared::cta.b64 P1, [%0], %1, 0x989680;\n\t" \
            "@P1 bra.uni D_%=;\n\t"                                          \
            "bra.uni W_%=;\n\t"                                              \
            "D_%=:\n\t}" :: "r"(mb), "r"(par) : "memory");                   \
    }                                                                        \
} while (0)

__device__ __forceinline__ uint32_t h2_as_u32(__half2 v) {
    return *reinterpret_cast<uint32_t*>(&v);
}

// m16n8k16 fp16 mma, fp32 accumulate (fallback + attention)
__device__ __forceinline__ void mma_f16(float* d, const uint32_t* a, const uint32_t* b) {
    asm volatile("mma.sync.aligned.m16n8k16.row.col.f32.f16.f16.f32 "
        "{%0,%1,%2,%3}, {%4,%5,%6,%7}, {%8,%9}, {%0,%1,%2,%3};"
        : "+f"(d[0]), "+f"(d[1]), "+f"(d[2]), "+f"(d[3])
        : "r"(a[0]), "r"(a[1]), "r"(a[2]), "r"(a[3]), "r"(b[0]), "r"(b[1]));
}

// ---------------- board (B,C,8,8) -> xin (B*64, KPAD) fp16 --------------------
__global__ void board_transpose_kernel(const float* __restrict__ board) {
    __shared__ float tile[NC * 65];
    int b = blockIdx.x;
    const float* src = board + (size_t)b * NC * SEQ;
    for (int i = threadIdx.x; i < NC * SEQ; i += blockDim.x) {
        int c = i >> 6, s = i & 63;
        tile[c * 65 + s] = src[i];
    }
    __syncthreads();
    __half* dst = g_xin + (size_t)b * SEQ * KPAD;
    for (int i = threadIdx.x; i < SEQ * KPAD; i += blockDim.x) {
        int s = i >> 7, c = i & 127;
        dst[i] = (c < NC) ? __float2half(tile[c * 65 + s]) : __float2half(0.f);
    }
}

// ---- weight transpose W(R x Cw) -> Wt(Cw x Rpad) fp16, natural K order -------
__global__ void transpose_kernel(const float* __restrict__ W, __half* __restrict__ Wt,
                                 int R, int Cw, int Rpad) {
    __shared__ float t[32][33];
    int bx = blockIdx.x * 32;
    int by = blockIdx.y * 32;
    int tx = threadIdx.x, ty = threadIdx.y;
    #pragma unroll
    for (int i = 0; i < 4; i++) {
        int r = by + ty + i * 8, c = bx + tx;
        t[ty + i * 8][tx] = (r < R) ? W[(size_t)r * Cw + c] : 0.f;
    }
    __syncthreads();
    #pragma unroll
    for (int i = 0; i < 4; i++) {
        int c = bx + ty + i * 8;   // n (output row)
        int k = by + tx;           // k (natural order)
        Wt[(size_t)c * Rpad + k] = __float2half(t[tx][ty + i * 8]);
    }
}

__global__ void concat_bias_kernel(const float* __restrict__ bq,
                                   const float* __restrict__ bk,
                                   const float* __restrict__ bv) {
    int i = blockIdx.x * blockDim.x + threadIdx.x;
    if (i >= 3 * ND) return;
    g_bqkv[i] = (i < ND) ? bq[i] : (i < 2 * ND) ? bk[i - ND] : bv[i - 2 * ND];
}

// ---------------- fallback fp16 mma.sync GEMM ----------------------------------
__global__ __launch_bounds__(256, 2)
void gemm_mma_kernel(const __half* __restrict__ A, const __half* __restrict__ Bt,
                     const float* __restrict__ bias,
                     const __half* __restrict__ resh, const float* __restrict__ pos,
                     __half* __restrict__ Ch, int K, int ldc)
{
    extern __shared__ uint32_t dynsm[];
    uint32_t* As = dynsm;
    uint32_t* Bs = dynsm + NSTG * ASTG;

    const int tid = threadIdx.x;
    const int lane = tid & 31, wid = tid >> 5;
    const int g = lane >> 2, t = lane & 3;
    const int wm = wid >> 2, wn = wid & 3;
    const int bm = blockIdx.y * 128, bn = blockIdx.x * 128;

    const int lrow = tid >> 1, seg = tid & 1;
    const __half* pA = A  + (size_t)(bm + lrow) * K + seg * 16;
    const __half* pB = Bt + (size_t)(bn + lrow) * K + seg * 16;
    uint32_t aOff[2], bOff[2];
    {
        const uint32_t aBase = smem_u32(As), bBase = smem_u32(Bs);
        #pragma unroll
        for (int q = 0; q < 2; q++) {
            aOff[q] = aBase + (uint32_t)(lrow * PADKA + seg * 8 + q * 4) * 4;
            bOff[q] = bBase + (uint32_t)(lrow * PADKB + seg * 8 + q * 4) * 4;
        }
    }

    const int nk = K / 32;

    float acc[4][4][4];
    #pragma unroll
    for (int i = 0; i < 4; i++)
        #pragma unroll
        for (int j = 0; j < 4; j++)
            #pragma unroll
            for (int r = 0; r < 4; r++) acc[i][j][r] = 0.f;

    #pragma unroll
    for (int st = 0; st < 3; st++) {
        const uint32_t soa = (uint32_t)st * (ASTG * 4);
        const uint32_t sob = (uint32_t)st * (BSTG * 4);
        const int k0 = st * 32;
        #pragma unroll
        for (int q = 0; q < 2; q++) {
            cp_async16(aOff[q] + soa, pA + k0 + q * 8);
            cp_async16(bOff[q] + sob, pB + k0 + q * 8);
        }
        CP_COMMIT();
    }

    for (int it = 0; it < nk; it++) {
        const int s = it & 3;
        const int rem = nk - 1 - it;
        if (rem >= 2)      { CP_WAIT(2); }
        else if (rem == 1) { CP_WAIT(1); }
        else               { CP_WAIT(0); }
        __syncthreads();

        if (it + 3 < nk) {
            const int s2 = (it + 3) & 3;
            const uint32_t soa = (uint32_t)s2 * (ASTG * 4);
            const uint32_t sob = (uint32_t)s2 * (BSTG * 4);
            const int k0 = (it + 3) * 32;
            #pragma unroll
            for (int q = 0; q < 2; q++) {
                cp_async16(aOff[q] + soa, pA + k0 + q * 8);
                cp_async16(bOff[q] + sob, pB + k0 + q * 8);
            }
            CP_COMMIT();
        }

        const uint32_t* Ab = As + s * ASTG;
        const uint32_t* Bb = Bs + s * BSTG;
        #pragma unroll
        for (int gk = 0; gk < 2; gk++) {
            const int kb = gk * 8;
            uint32_t a[4][4];
            uint32_t b[4][2];
            #pragma unroll
            for (int i = 0; i < 4; i++) {
                int r = (wm * 64 + i * 16 + g) * PADKA + kb + t;
                a[i][0] = Ab[r];
                a[i][1] = Ab[r + 8 * PADKA];
                a[i][2] = Ab[r + 4];
                a[i][3] = Ab[r + 8 * PADKA + 4];
            }
            #pragma unroll
            for (int j = 0; j < 4; j++) {
                int c = (wn * 32 + j * 8 + g) * PADKB + kb + t;
                b[j][0] = Bb[c];
                b[j][1] = Bb[c + 4];
            }
            #pragma unroll
            for (int i = 0; i < 4; i++)
                #pragma unroll
                for (int j = 0; j < 4; j++)
                    mma_f16(acc[i][j], a[i], b[j]);
        }
    }

    #pragma unroll
    for (int i = 0; i < 4; i++) {
        int r0 = bm + wm * 64 + i * 16 + g;
        #pragma unroll
        for (int j = 0; j < 4; j++) {
            int cg = bn + wn * 32 + j * 8 + t * 2;
            float2 b2 = *(const float2*)&bias[cg];
            float o00 = acc[i][j][0] + b2.x, o01 = acc[i][j][1] + b2.y;
            float o10 = acc[i][j][2] + b2.x, o11 = acc[i][j][3] + b2.y;
            size_t row0 = (size_t)r0 * ldc + cg;
            size_t row1 = (size_t)(r0 + 8) * ldc + cg;
            if (resh) {
                __half2 x0 = *(const __half2*)&resh[row0];
                __half2 x1 = *(const __half2*)&resh[row1];
                o00 += __half2float(x0.x); o01 += __half2float(x0.y);
                o10 += __half2float(x1.x); o11 += __half2float(x1.y);
            }
            if (pos) {
                float2 p0 = *(const float2*)&pos[(size_t)(r0 & 63) * ND + cg];
                float2 p1 = *(const float2*)&pos[(size_t)((r0 + 8) & 63) * ND + cg];
                o00 += p0.x; o01 += p0.y; o10 += p1.x; o11 += p1.y;
            }
            *(__half2*)&Ch[row0] = __floats2half2_rn(o00, o01);
            *(__half2*)&Ch[row1] = __floats2half2_rn(o10, o11);
        }
    }
}

// ---------------- tcgen05 SS f16 GEMM (sm_103a arch-specific path) ------------
// CTA 128(M) x 256(N); K64 chunks; 2-stage; D in TMEM (256 cols fp32).
// relinquish_alloc_permit after alloc -> 2 CTAs/SM co-resident.
__global__ __launch_bounds__(256, 2)
void gemm_tc_kernel(const __half* __restrict__ A, const __half* __restrict__ Bt,
                    const float* __restrict__ bias,
                    const __half* __restrict__ resh, const float* __restrict__ pos,
                    __half* __restrict__ Ch, int K, int ldc)
{
#if defined(__CUDA_ARCH_SPECIFIC__) && (__CUDA_ARCH__ >= 1000)
    extern __shared__ char smem[];
    const uint32_t sb = smem_u32(smem);
    const int tid = threadIdx.x, lane = tid & 31, wid = tid >> 5;
    const int bm = blockIdx.y * 128, bn = blockIdx.x * 256;

    if (wid == 0) {
        asm volatile("tcgen05.alloc.cta_group::1.sync.aligned.shared::cta.b32 [%0], %1;"
                     :: "r"(sb), "r"(256u) : "memory");
        asm volatile("tcgen05.relinquish_alloc_permit.cta_group::1.sync.aligned;");
    }
    if (tid == 0) {
        asm volatile("mbarrier.init.shared.b64 [%0], %1;" :: "r"(sb + 8), "r"(1u) : "memory");
        asm volatile("mbarrier.init.shared.b64 [%0], %1;" :: "r"(sb + 16), "r"(1u) : "memory");
    }
    __syncthreads();
    uint32_t tmem;
    asm volatile("ld.shared.b32 %0, [%1];" : "=r"(tmem) : "r"(sb));

    // loaders: thread -> row lr (0..127), half hf covers 4 granules of 16B
    const int lr = tid >> 1, hf = tid & 1;
    const __half* pA  = A  + (size_t)(bm + lr) * K;
    const __half* pB0 = Bt + (size_t)(bn + lr) * K;
    const __half* pB1 = Bt + (size_t)(bn + lr + 128) * K;
    uint32_t aDst[4], bDst0[4], bDst1[4];
    int gsrc[4];
    #pragma unroll
    for (int q = 0; q < 4; q++) {
        int gq = hf * 4 + q;
        int sw = (gq ^ (lr & 7)) * 16;
        gsrc[q] = gq * 8;
        aDst[q]  = sb + TC_A_OFF + (uint32_t)lr * 128 + sw;
        bDst0[q] = sb + TC_B_OFF + (uint32_t)lr * 128 + sw;
        bDst1[q] = sb + TC_B_OFF + (uint32_t)(lr + 128) * 128 + sw;
    }

    const int nk = K / 64;
    const uint32_t idesc = (1u << 4) | ((256u / 8u) << 17) | ((128u / 16u) << 24);
    const uint64_t DESC_BASE =
        (uint64_t(2) << 61) | (uint64_t(1) << 46) | (uint64_t(64) << 32) | (uint64_t(1) << 16);

    // prologue: fill stages 0 (+1)
    #pragma unroll
    for (int st = 0; st < 2; st++) {
        if (st < nk) {
            const int k0 = st * 64;
            #pragma unroll
            for (int q = 0; q < 4; q++) {
                cp_async16(aDst[q]  + st * TC_ASTG, pA  + k0 + gsrc[q]);
                cp_async16(bDst0[q] + st * TC_BSTG, pB0 + k0 + gsrc[q]);
                cp_async16(bDst1[q] + st * TC_BSTG, pB1 + k0 + gsrc[q]);
            }
            CP_COMMIT();
        }
    }

    int ph0 = 0, ph1 = 0;
    for (int it = 0; it < nk; it++) {
        const int buf = it & 1;
        if (it + 1 < nk) { CP_WAIT(1); } else { CP_WAIT(0); }
        __syncthreads();

        if (wid == 0) {
            uint32_t pr;
            asm volatile("{\n\t.reg .pred p;\n\telect.sync _|p, 0xFFFFFFFF;\n\t"
                         "selp.b32 %0, 1, 0, p;\n\t}" : "=r"(pr));
            if (pr) {
                uint64_t ad = DESC_BASE | (((uint64_t)((sb + TC_A_OFF + buf * TC_ASTG) >> 4)) & 0x3FFF);
                uint64_t bd = DESC_BASE | (((uint64_t)((sb + TC_B_OFF + buf * TC_BSTG) >> 4)) & 0x3FFF);
                #pragma unroll
                for (int s = 0; s < 4; s++) {
                    uint32_t en = ((it > 0) || (s > 0)) ? 1u : 0u;
                    asm volatile("{\n\t.reg .pred p;\n\tsetp.ne.u32 p, %5, 0;\n\t"
                        "tcgen05.mma.cta_group::1.kind::f16 [%0], %1, %2, %3, {%4, %4, %4, %4}, p;\n\t}"
                        :: "r"(tmem), "l"(ad + 2 * s), "l"(bd + 2 * s), "r"(idesc),
                           "r"(0u), "r"(en) : "memory");
                }
                asm volatile(
                    "tcgen05.commit.cta_group::1.mbarrier::arrive::one.shared::cluster.b64 [%0];"
                    :: "r"(sb + 8 + (uint32_t)buf * 8) : "memory");
            }
        }

        if (it + 2 < nk) {
            // wait for chunk `it`'s MMAs (this buffer) before refilling it
            uint32_t mb = sb + 8 + (uint32_t)buf * 8;
            uint32_t parity = buf ? (uint32_t)ph1 : (uint32_t)ph0;
            MBAR_WAIT(mb, parity);
            if (buf) ph1 ^= 1; else ph0 ^= 1;

            const int k0 = (it + 2) * 64;
            #pragma unroll
            for (int q = 0; q < 4; q++) {
                cp_async16(aDst[q]  + buf * TC_ASTG, pA  + k0 + gsrc[q]);
                cp_async16(bDst0[q] + buf * TC_BSTG, pB0 + k0 + gsrc[q]);
                cp_async16(bDst1[q] + buf * TC_BSTG, pB1 + k0 + gsrc[q]);
            }
            CP_COMMIT();
        }
    }

    // final wait on the last commit (covers all prior MMAs)
    {
        const int buf = (nk - 1) & 1;
        uint32_t mb = sb + 8 + (uint32_t)buf * 8;
        uint32_t parity = buf ? (uint32_t)ph1 : (uint32_t)ph0;
        MBAR_WAIT(mb, parity);
    }
    asm volatile("tcgen05.fence::after_thread_sync;" ::: "memory");

    // epilogue: warp w -> rows (w&3)*32+lane, cols (w>>2)*128 + c*32
    const int sub = wid & 3, half = wid >> 2;
    const int rg = bm + sub * 32 + lane;
    #pragma unroll
    for (int c = 0; c < 4; c++) {
        const int c0 = half * 128 + c * 32;
        uint32_t dr[32];
        asm volatile("tcgen05.ld.sync.aligned.32x32b.x32.b32 "
            "{%0, %1, %2, %3, %4, %5, %6, %7, %8, %9, %10, %11, %12, %13, %14, %15, "
            " %16, %17, %18, %19, %20, %21, %22, %23, %24, %25, %26, %27, %28, %29, %30, %31}, [%32];"
            : "=r"(dr[0]),  "=r"(dr[1]),  "=r"(dr[2]),  "=r"(dr[3]),
              "=r"(dr[4]),  "=r"(dr[5]),  "=r"(dr[6]),  "=r"(dr[7]),
              "=r"(dr[8]),  "=r"(dr[9]),  "=r"(dr[10]), "=r"(dr[11]),
              "=r"(dr[12]), "=r"(dr[13]), "=r"(dr[14]), "=r"(dr[15]),
              "=r"(dr[16]), "=r"(dr[17]), "=r"(dr[18]), "=r"(dr[19]),
              "=r"(dr[20]), "=r"(dr[21]), "=r"(dr[22]), "=r"(dr[23]),
              "=r"(dr[24]), "=r"(dr[25]), "=r"(dr[26]), "=r"(dr[27]),
              "=r"(dr[28]), "=r"(dr[29]), "=r"(dr[30]), "=r"(dr[31])
            : "r"(tmem + c0));
        asm volatile("tcgen05.wait::ld.sync.aligned;" ::: "memory");

        const int cb = bn + c0;
        const size_t rowoff = (size_t)rg * ldc + cb;
        float v[32];
        #pragma unroll
        for (int q = 0; q < 8; q++) {
            float4 b4 = *(const float4*)&bias[cb + q * 4];
            v[q*4+0] = __uint_as_float(dr[q*4+0]) + b4.x;
            v[q*4+1] = __uint_as_float(dr[q*4+1]) + b4.y;
            v[q*4+2] = __uint_as_float(dr[q*4+2]) + b4.z;
            v[q*4+3] = __uint_as_float(dr[q*4+3]) + b4.w;
        }
        if (resh) {
            #pragma unroll
            for (int q = 0; q < 4; q++) {
                uint4 rh = *(const uint4*)&resh[rowoff + q * 8];
                const __half2* hp = (const __half2*)&rh;
                #pragma unroll
                for (int e = 0; e < 4; e++) {
                    float2 f = __half22float2(hp[e]);
                    v[q * 8 + e * 2]     += f.x;
                    v[q * 8 + e * 2 + 1] += f.y;
                }
            }
        }
        if (pos) {
            const float* pp = pos + (size_t)(rg & 63) * ND + cb;
            #pragma unroll
            for (int j = 0; j < 32; j += 4) {
                float4 p4 = *(const float4*)&pp[j];
                v[j] += p4.x; v[j+1] += p4.y; v[j+2] += p4.z; v[j+3] += p4.w;
            }
        }
        #pragma unroll
        for (int q = 0; q < 4; q++) {
            __half2 h[4];
            #pragma unroll
            for (int e = 0; e < 4; e++)
                h[e] = __floats2half2_rn(v[q * 8 + e * 2], v[q * 8 + e * 2 + 1]);
            *(uint4*)&Ch[rowoff + q * 8] = *(uint4*)h;
        }
    }

    asm volatile("tcgen05.fence::before_thread_sync;" ::: "memory");
    __syncthreads();
    if (tid == 0) {
        asm volatile("mbarrier.inval.shared.b64 [%0];" :: "r"(sb + 8) : "memory");
        asm volatile("mbarrier.inval.shared.b64 [%0];" :: "r"(sb + 16) : "memory");
    }
    __syncthreads();
    if (wid == 0) {
        asm volatile("tcgen05.dealloc.cta_group::1.sync.aligned.b32 %0, %1;" :: "r"(tmem), "r"(256u));
    }
#endif
}

// ---------------- attention: fp16 MMA flash kernel, one (b,h) per block -------
#define TPITCH 36

__global__ __launch_bounds__(128)
void attn_kernel(const float* __restrict__ rel_bias)
{
    __shared__ uint32_t qs[64 * TPITCH];
    __shared__ uint32_t ks[64 * TPITCH];
    __shared__ uint32_t vs[64 * TPITCH];

    const int h = blockIdx.x, b = blockIdx.y;
    const int tid = threadIdx.x;
    const int lane = tid & 31, w = tid >> 5;
    const int g = lane >> 2, t = lane & 3;

    const __half* qbase = g_qkvh + (size_t)b * SEQ * (3 * ND) + h * 64;

    __half* vsH = (__half*)vs;
    for (int idx = tid; idx < 512; idx += 128) {
        int s = idx >> 3, dg = idx & 7;
        const size_t r = (size_t)s * (3 * ND) + dg * 8;
        uint4 vq = *(const uint4*)(qbase + r);
        uint4 vk = *(const uint4*)(qbase + r + ND);
        *(uint4*)&qs[s * TPITCH + dg * 4] = vq;
        *(uint4*)&ks[s * TPITCH + dg * 4] = vk;
        uint4 vv = *(const uint4*)(qbase + r + 2 * ND);
        __half hv[8];
        *(uint4*)hv = vv;
        #pragma unroll
        for (int q = 0; q < 8; q++)
            vsH[(dg * 8 + q) * (TPITCH * 2) + s] = hv[q];
    }
    __syncthreads();

    float sc[8][4];
    #pragma unroll
    for (int j = 0; j < 8; j++)
        #pragma unroll
        for (int r = 0; r < 4; r++) sc[j][r] = 0.f;

    const int arow0 = (w * 16 + g) * TPITCH;
    const int arow1 = (w * 16 + g + 8) * TPITCH;
    #pragma unroll
    for (int kt = 0; kt < 4; kt++) {
        uint32_t a[4];
        a[0] = qs[arow0 + kt * 8 + t];
        a[1] = qs[arow1 + kt * 8 + t];
        a[2] = qs[arow0 + kt * 8 + t + 4];
        a[3] = qs[arow1 + kt * 8 + t + 4];
        #pragma unroll
        for (int j = 0; j < 8; j++) {
            uint32_t bf[2];
            int br = (j * 8 + g) * TPITCH + kt * 8 + t;
            bf[0] = ks[br];
            bf[1] = ks[br + 4];
            mma_f16(sc[j], a, bf);
        }
    }

    const float* rb = rel_bias + (size_t)h * 4096 + (size_t)(w * 16 + g) * 64;
    #pragma unroll
    for (int j = 0; j < 8; j++) {
        float2 b0 = *(const float2*)&rb[j * 8 + 2 * t];
        float2 b1 = *(const float2*)&rb[8 * 64 + j * 8 + 2 * t];
        sc[j][0] = sc[j][0] * 0.125f + b0.x;
        sc[j][1] = sc[j][1] * 0.125f + b0.y;
        sc[j][2] = sc[j][2] * 0.125f + b1.x;
        sc[j][3] = sc[j][3] * 0.125f + b1.y;
    }

    float m0 = -1e30f, m1 = -1e30f;
    #pragma unroll
    for (int j = 0; j < 8; j++) {
        m0 = fmaxf(m0, fmaxf(sc[j][0], sc[j][1]));
        m1 = fmaxf(m1, fmaxf(sc[j][2], sc[j][3]));
    }
    m0 = fmaxf(m0, __shfl_xor_sync(0xffffffffu, m0, 1));
    m0 = fmaxf(m0, __shfl_xor_sync(0xffffffffu, m0, 2));
    m1 = fmaxf(m1, __shfl_xor_sync(0xffffffffu, m1, 1));
    m1 = fmaxf(m1, __shfl_xor_sync(0xffffffffu, m1, 2));
    float s0 = 0.f, s1 = 0.f;
    #pragma unroll
    for (int j = 0; j < 8; j++) {
        sc[j][0] = __expf(sc[j][0] - m0); s0 += sc[j][0];
        sc[j][1] = __expf(sc[j][1] - m0); s0 += sc[j][1];
        sc[j][2] = __expf(sc[j][2] - m1); s1 += sc[j][2];
        sc[j][3] = __expf(sc[j][3] - m1); s1 += sc[j][3];
    }
    s0 += __shfl_xor_sync(0xffffffffu, s0, 1);
    s0 += __shfl_xor_sync(0xffffffffu, s0, 2);
    s1 += __shfl_xor_sync(0xffffffffu, s1, 1);
    s1 += __shfl_xor_sync(0xffffffffu, s1, 2);
    const float inv0 = 1.f / s0, inv1 = 1.f / s1;

    uint32_t pa[4][4];
    #pragma unroll
    for (int kt = 0; kt < 4; kt++) {
        pa[kt][0] = h2_as_u32(__floats2half2_rn(sc[2*kt][0]   * inv0, sc[2*kt][1]   * inv0));
        pa[kt][1] = h2_as_u32(__floats2half2_rn(sc[2*kt][2]   * inv1, sc[2*kt][3]   * inv1));
        pa[kt][2] = h2_as_u32(__floats2half2_rn(sc[2*kt+1][0] * inv0, sc[2*kt+1][1] * inv0));
        pa[kt][3] = h2_as_u32(__floats2half2_rn(sc[2*kt+1][2] * inv1, sc[2*kt+1][3] * inv1));
    }

    float oc[8][4];
    #pragma unroll
    for (int j = 0; j < 8; j++)
        #pragma unroll
        for (int r = 0; r < 4; r++) oc[j][r] = 0.f;

    #pragma unroll
    for (int kt = 0; kt < 4; kt++) {
        #pragma unroll
        for (int j = 0; j < 8; j++) {
            uint32_t bf[2];
            int br = (j * 8 + g) * TPITCH + kt * 8 + t;
            bf[0] = vs[br];
            bf[1] = vs[br + 4];
            mma_f16(oc[j], pa[kt], bf);
        }
    }

    __half* ob0 = g_o + (size_t)(b * SEQ + w * 16 + g) * ND + h * 64;
    __half* ob1 = ob0 + (size_t)8 * ND;
    #pragma unroll
    for (int j = 0; j < 8; j++) {
        *(__half2*)&ob0[j * 8 + 2 * t] = __floats2half2_rn(oc[j][0], oc[j][1]);
        *(__half2*)&ob1[j * 8 + 2 * t] = __floats2half2_rn(oc[j][2], oc[j][3]);
    }
}

// ---------------- LayerNorm: warp-per-row (fp16 in, fp32 out) -----------------
__global__ __launch_bounds__(256)
void ln_kernel(const float* __restrict__ gamma, const float* __restrict__ beta,
               float* __restrict__ out)
{
    const int wid = threadIdx.x >> 5, lane = threadIdx.x & 31;
    const size_t row = ((size_t)blockIdx.x * 8 + wid) * ND;
    const int base = lane * 32;

    float v[32];
    #pragma unroll
    for (int q = 0; q < 4; q++) {
        uint4 raw = *(const uint4*)&g_yh[row + base + q * 8];
        const __half2* hp = (const __half2*)&raw;
        #pragma unroll
        for (int e = 0; e < 4; e++) {
            float2 f = __half22float2(hp[e]);
            v[q * 8 + e * 2]     = f.x;
            v[q * 8 + e * 2 + 1] = f.y;
        }
    }

    float s = 0.f;
    #pragma unroll
    for (int j = 0; j < 32; j++) s += v[j];
    #pragma unroll
    for (int o = 16; o > 0; o >>= 1) s += __shfl_xor_sync(0xffffffffu, s, o);
    const float mu = s * (1.f / ND);

    float sq = 0.f;
    #pragma unroll
    for (int j = 0; j < 32; j++) { v[j] -= mu; sq += v[j] * v[j]; }
    #pragma unroll
    for (int o = 16; o > 0; o >>= 1) sq += __shfl_xor_sync(0xffffffffu, sq, o);
    const float inv = rsqrtf(sq * (1.f / ND) + 1e-5f);

    #pragma unroll
    for (int q = 0; q < 8; q++) {
        float4 g4 = *(const float4*)&gamma[base + q * 4];
        float4 b4 = *(const float4*)&beta[base + q * 4];
        float4 o4;
        o4.x = v[q*4+0] * inv * g4.x + b4.x;
        o4.y = v[q*4+1] * inv * g4.y + b4.y;
        o4.z = v[q*4+2] * inv * g4.z + b4.z;
        o4.w = v[q*4+3] * inv * g4.w + b4.w;
        *(float4*)&out[row + base + q * 4] = o4;
    }
}

// ---------------- launch -------------------------------------------------------
extern "C" void kernel_launch(void* const* d_in, const int* in_sizes, int n_in,
                              void* d_out, int out_size)
{
    const float* board = (const float*)d_in[0];
    const float* embW  = (const float*)d_in[1];
    const float* embB  = (const float*)d_in[2];
    const float* pos   = (const float*)d_in[3];
    const float* Wq    = (const float*)d_in[4];
    const float* bq    = (const float*)d_in[5];
    const float* Wk    = (const float*)d_in[6];
    const float* bk    = (const float*)d_in[7];
    const float* Wv    = (const float*)d_in[8];
    const float* bv    = (const float*)d_in[9];
    const float* Wo    = (const float*)d_in[10];
    const float* bo    = (const float*)d_in[11];
    const float* relb  = (const float*)d_in[12];
    const float* lng   = (const float*)d_in[13];
    const float* lnb   = (const float*)d_in[14];
    float* out = (float*)d_out;

    __half *xin, *wt, *xh, *qkvh, *o, *yh;
    float *bqkv;
    cudaGetSymbolAddress((void**)&xin,  g_xin);
    cudaGetSymbolAddress((void**)&wt,   g_Wt);
    cudaGetSymbolAddress((void**)&bqkv, g_bqkv);
    cudaGetSymbolAddress((void**)&xh,   g_xh);
    cudaGetSymbolAddress((void**)&qkvh, g_qkvh);
    cudaGetSymbolAddress((void**)&o,    g_o);
    cudaGetSymbolAddress((void**)&yh,   g_yh);

    cudaFuncSetAttribute(gemm_mma_kernel,
                         cudaFuncAttributeMaxDynamicSharedMemorySize, GSMEM);
    cudaFuncSetAttribute(gemm_tc_kernel,
                         cudaFuncAttributeMaxDynamicSharedMemorySize, TC_SMEM);

    // Runtime dispatch: tcgen05 body exists only in the sm_103a cubin.
    cudaFuncAttributes fa{};
    cudaFuncGetAttributes(&fa, gemm_tc_kernel);
    const bool use_tc = (fa.numRegs >= 32);

    board_transpose_kernel<<<NB, 256>>>(board);
    concat_bias_kernel<<<(3 * ND + 255) / 256, 256>>>(bq, bk, bv);

    dim3 tb(32, 8);

    transpose_kernel<<<dim3(ND / 32, KPAD / 32), tb>>>(embW, wt, NC, ND, KPAD);
    if (use_tc)
        gemm_tc_kernel<<<dim3(ND / 256, MR / 128), 256, TC_SMEM>>>(
            xin, wt, embB, nullptr, pos, xh, KPAD, ND);
    else
        gemm_mma_kernel<<<dim3(ND / 128, MR / 128), 256, GSMEM>>>(
            xin, wt, embB, nullptr, pos, xh, KPAD, ND);

    transpose_kernel<<<dim3(ND / 32, ND / 32), tb>>>(Wq, wt,                 ND, ND, ND);
    transpose_kernel<<<dim3(ND / 32, ND / 32), tb>>>(Wk, wt + (size_t)ND*ND,   ND, ND, ND);
    transpose_kernel<<<dim3(ND / 32, ND / 32), tb>>>(Wv, wt + (size_t)2*ND*ND, ND, ND, ND);
    if (use_tc)
        gemm_tc_kernel<<<dim3(3 * ND / 256, MR / 128), 256, TC_SMEM>>>(
            xh, wt, bqkv, nullptr, nullptr, qkvh, ND, 3 * ND);
    else
        gemm_mma_kernel<<<dim3(3 * ND / 128, MR / 128), 256, GSMEM>>>(
            xh, wt, bqkv, nullptr, nullptr, qkvh, ND, 3 * ND);

    attn_kernel<<<dim3(NH, NB), 128>>>(relb);

    transpose_kernel<<<dim3(ND / 32, ND / 32), tb>>>(Wo, wt, ND, ND, ND);
    if (use_tc)
        gemm_tc_kernel<<<dim3(ND / 256, MR / 128), 256, TC_SMEM>>>(
            o, wt, bo, xh, nullptr, yh, ND, ND);
    else
        gemm_mma_kernel<<<dim3(ND / 128, MR / 128), 256, GSMEM>>>(
            o, wt, bo, xh, nullptr, yh, ND, ND);

    ln_kernel<<<MR / 8, 256>>>(lng, lnb, out);
}

// round 17
// speedup vs baseline: 1.4985x; 1.3030x over previous
#include <cuda_runtime.h>
#include <cuda_fp16.h>
#include <cstdint>
#include <math.h>

#define NB   1024
#define NC   119
#define ND   1024
#define NH   16
#define SEQ  64
#define MR   (NB*SEQ)     // 65536 rows
#define KPAD 128

// ---- mma.sync fallback GEMM tiling: CTA 128x128, BK=32 halves -----------------
#define PADKA 20
#define PADKB 24
#define ASTG  (128 * PADKA)
#define BSTG  (128 * PADKB)
#define NSTG  4
#define GSMEM ((ASTG + BSTG) * NSTG * 4)   // 90112 bytes

// ---- tcgen05 GEMM: CTA 128(M) x 256(N), K32 chunks (SW64), 4-stage, 2 CTA/SM --
#define TC_A_OFF  1024u
#define TC_ASTG   8192u                      // 128 rows x 64B
#define TC_B_OFF  (1024u + 4u * 8192u)       // 33792
#define TC_BSTG   16384u                     // 256 rows x 64B
#define TC_SMEM   (TC_B_OFF + 4u * 16384u)   // 99328 bytes

// ---------------- scratch ----------------------------------------------------
__device__ __half g_xin [(size_t)MR * KPAD];
__device__ __half g_Wt  [(size_t)3 * ND * ND];   // transposed fp16 weights (natural K)
__device__ float  g_bqkv[3 * ND];
__device__ __half g_xh  [(size_t)MR * ND];       // fp16 x (embed out, residual)
__device__ __half g_qkvh[(size_t)MR * 3 * ND];   // fp16 qkv
__device__ __half g_o   [(size_t)MR * ND];
__device__ __half g_yh  [(size_t)MR * ND];       // fp16 pre-LN y

// ---------------- helpers -----------------------------------------------------
__device__ __forceinline__ uint32_t smem_u32(const void* p) {
    uint32_t a;
    asm("{ .reg .u64 t; cvta.to.shared.u64 t, %1; cvt.u32.u64 %0, t; }" : "=r"(a) : "l"(p));
    return a;
}
__device__ __forceinline__ void cp_async16(uint32_t saddr, const void* gptr) {
    asm volatile("cp.async.cg.shared.global [%0], [%1], 16;" :: "r"(saddr), "l"(gptr));
}
#define CP_COMMIT() asm volatile("cp.async.commit_group;")
#define CP_WAIT(n)  asm volatile("cp.async.wait_group %0;" :: "n"(n))

#define MBAR_WAIT(mb, par) do {                                              \
    uint32_t _d;                                                             \
    asm volatile("{\n\t.reg .pred p;\n\t"                                    \
        "mbarrier.try_wait.parity.acquire.cta.shared::cta.b64 p, [%1], %2;\n\t" \
        "selp.b32 %0, 1, 0, p;\n\t}" : "=r"(_d) : "r"(mb), "r"(par) : "memory"); \
    if (!_d) {                                                               \
        asm volatile("{\n\t.reg .pred P1;\n\t"                               \
            "W_%=:\n\t"                                                      \
            "mbarrier.try_wait.parity.acquire.cta.shared::cta.b64 P1, [%0], %1, 0x989680;\n\t" \
            "@P1 bra.uni D_%=;\n\t"                                          \
            "bra.uni W_%=;\n\t"                                              \
            "D_%=:\n\t}" :: "r"(mb), "r"(par) : "memory");                   \
    }                                                                        \
} while (0)

__device__ __forceinline__ uint32_t h2_as_u32(__half2 v) {
    return *reinterpret_cast<uint32_t*>(&v);
}

// m16n8k16 fp16 mma, fp32 accumulate (fallback + attention)
__device__ __forceinline__ void mma_f16(float* d, const uint32_t* a, const uint32_t* b) {
    asm volatile("mma.sync.aligned.m16n8k16.row.col.f32.f16.f16.f32 "
        "{%0,%1,%2,%3}, {%4,%5,%6,%7}, {%8,%9}, {%0,%1,%2,%3};"
        : "+f"(d[0]), "+f"(d[1]), "+f"(d[2]), "+f"(d[3])
        : "r"(a[0]), "r"(a[1]), "r"(a[2]), "r"(a[3]), "r"(b[0]), "r"(b[1]));
}

// ---------------- board (B,C,8,8) -> xin (B*64, KPAD) fp16 --------------------
__global__ void board_transpose_kernel(const float* __restrict__ board) {
    __shared__ float tile[NC * 65];
    int b = blockIdx.x;
    const float* src = board + (size_t)b * NC * SEQ;
    for (int i = threadIdx.x; i < NC * SEQ; i += blockDim.x) {
        int c = i >> 6, s = i & 63;
        tile[c * 65 + s] = src[i];
    }
    __syncthreads();
    __half* dst = g_xin + (size_t)b * SEQ * KPAD;
    for (int i = threadIdx.x; i < SEQ * KPAD; i += blockDim.x) {
        int s = i >> 7, c = i & 127;
        dst[i] = (c < NC) ? __float2half(tile[c * 65 + s]) : __float2half(0.f);
    }
}

// ---- weight transpose W(R x Cw) -> Wt(Cw x Rpad) fp16, natural K order -------
__global__ void transpose_kernel(const float* __restrict__ W, __half* __restrict__ Wt,
                                 int R, int Cw, int Rpad) {
    __shared__ float t[32][33];
    int bx = blockIdx.x * 32;
    int by = blockIdx.y * 32;
    int tx = threadIdx.x, ty = threadIdx.y;
    #pragma unroll
    for (int i = 0; i < 4; i++) {
        int r = by + ty + i * 8, c = bx + tx;
        t[ty + i * 8][tx] = (r < R) ? W[(size_t)r * Cw + c] : 0.f;
    }
    __syncthreads();
    #pragma unroll
    for (int i = 0; i < 4; i++) {
        int c = bx + ty + i * 8;   // n (output row)
        int k = by + tx;           // k (natural order)
        Wt[(size_t)c * Rpad + k] = __float2half(t[tx][ty + i * 8]);
    }
}

__global__ void concat_bias_kernel(const float* __restrict__ bq,
                                   const float* __restrict__ bk,
                                   const float* __restrict__ bv) {
    int i = blockIdx.x * blockDim.x + threadIdx.x;
    if (i >= 3 * ND) return;
    g_bqkv[i] = (i < ND) ? bq[i] : (i < 2 * ND) ? bk[i - ND] : bv[i - 2 * ND];
}

// ---------------- fallback fp16 mma.sync GEMM ----------------------------------
__global__ __launch_bounds__(256, 2)
void gemm_mma_kernel(const __half* __restrict__ A, const __half* __restrict__ Bt,
                     const float* __restrict__ bias,
                     const __half* __restrict__ resh, const float* __restrict__ pos,
                     __half* __restrict__ Ch, int K, int ldc)
{
    extern __shared__ uint32_t dynsm[];
    uint32_t* As = dynsm;
    uint32_t* Bs = dynsm + NSTG * ASTG;

    const int tid = threadIdx.x;
    const int lane = tid & 31, wid = tid >> 5;
    const int g = lane >> 2, t = lane & 3;
    const int wm = wid >> 2, wn = wid & 3;
    const int bm = blockIdx.y * 128, bn = blockIdx.x * 128;

    const int lrow = tid >> 1, seg = tid & 1;
    const __half* pA = A  + (size_t)(bm + lrow) * K + seg * 16;
    const __half* pB = Bt + (size_t)(bn + lrow) * K + seg * 16;
    uint32_t aOff[2], bOff[2];
    {
        const uint32_t aBase = smem_u32(As), bBase = smem_u32(Bs);
        #pragma unroll
        for (int q = 0; q < 2; q++) {
            aOff[q] = aBase + (uint32_t)(lrow * PADKA + seg * 8 + q * 4) * 4;
            bOff[q] = bBase + (uint32_t)(lrow * PADKB + seg * 8 + q * 4) * 4;
        }
    }

    const int nk = K / 32;

    float acc[4][4][4];
    #pragma unroll
    for (int i = 0; i < 4; i++)
        #pragma unroll
        for (int j = 0; j < 4; j++)
            #pragma unroll
            for (int r = 0; r < 4; r++) acc[i][j][r] = 0.f;

    #pragma unroll
    for (int st = 0; st < 3; st++) {
        const uint32_t soa = (uint32_t)st * (ASTG * 4);
        const uint32_t sob = (uint32_t)st * (BSTG * 4);
        const int k0 = st * 32;
        #pragma unroll
        for (int q = 0; q < 2; q++) {
            cp_async16(aOff[q] + soa, pA + k0 + q * 8);
            cp_async16(bOff[q] + sob, pB + k0 + q * 8);
        }
        CP_COMMIT();
    }

    for (int it = 0; it < nk; it++) {
        const int s = it & 3;
        const int rem = nk - 1 - it;
        if (rem >= 2)      { CP_WAIT(2); }
        else if (rem == 1) { CP_WAIT(1); }
        else               { CP_WAIT(0); }
        __syncthreads();

        if (it + 3 < nk) {
            const int s2 = (it + 3) & 3;
            const uint32_t soa = (uint32_t)s2 * (ASTG * 4);
            const uint32_t sob = (uint32_t)s2 * (BSTG * 4);
            const int k0 = (it + 3) * 32;
            #pragma unroll
            for (int q = 0; q < 2; q++) {
                cp_async16(aOff[q] + soa, pA + k0 + q * 8);
                cp_async16(bOff[q] + sob, pB + k0 + q * 8);
            }
            CP_COMMIT();
        }

        const uint32_t* Ab = As + s * ASTG;
        const uint32_t* Bb = Bs + s * BSTG;
        #pragma unroll
        for (int gk = 0; gk < 2; gk++) {
            const int kb = gk * 8;
            uint32_t a[4][4];
            uint32_t b[4][2];
            #pragma unroll
            for (int i = 0; i < 4; i++) {
                int r = (wm * 64 + i * 16 + g) * PADKA + kb + t;
                a[i][0] = Ab[r];
                a[i][1] = Ab[r + 8 * PADKA];
                a[i][2] = Ab[r + 4];
                a[i][3] = Ab[r + 8 * PADKA + 4];
            }
            #pragma unroll
            for (int j = 0; j < 4; j++) {
                int c = (wn * 32 + j * 8 + g) * PADKB + kb + t;
                b[j][0] = Bb[c];
                b[j][1] = Bb[c + 4];
            }
            #pragma unroll
            for (int i = 0; i < 4; i++)
                #pragma unroll
                for (int j = 0; j < 4; j++)
                    mma_f16(acc[i][j], a[i], b[j]);
        }
    }

    #pragma unroll
    for (int i = 0; i < 4; i++) {
        int r0 = bm + wm * 64 + i * 16 + g;
        #pragma unroll
        for (int j = 0; j < 4; j++) {
            int cg = bn + wn * 32 + j * 8 + t * 2;
            float2 b2 = *(const float2*)&bias[cg];
            float o00 = acc[i][j][0] + b2.x, o01 = acc[i][j][1] + b2.y;
            float o10 = acc[i][j][2] + b2.x, o11 = acc[i][j][3] + b2.y;
            size_t row0 = (size_t)r0 * ldc + cg;
            size_t row1 = (size_t)(r0 + 8) * ldc + cg;
            if (resh) {
                __half2 x0 = *(const __half2*)&resh[row0];
                __half2 x1 = *(const __half2*)&resh[row1];
                o00 += __half2float(x0.x); o01 += __half2float(x0.y);
                o10 += __half2float(x1.x); o11 += __half2float(x1.y);
            }
            if (pos) {
                float2 p0 = *(const float2*)&pos[(size_t)(r0 & 63) * ND + cg];
                float2 p1 = *(const float2*)&pos[(size_t)((r0 + 8) & 63) * ND + cg];
                o00 += p0.x; o01 += p0.y; o10 += p1.x; o11 += p1.y;
            }
            *(__half2*)&Ch[row0] = __floats2half2_rn(o00, o01);
            *(__half2*)&Ch[row1] = __floats2half2_rn(o10, o11);
        }
    }
}

// ---------------- tcgen05 SS f16 GEMM (sm_103a arch-specific path) ------------
// CTA 128(M) x 256(N); K32 chunks (SW64 layout); 4-stage ring, lead 3;
// D in TMEM (256 cols fp32); relinquish -> 2 CTAs/SM.
__global__ __launch_bounds__(256, 2)
void gemm_tc_kernel(const __half* __restrict__ A, const __half* __restrict__ Bt,
                    const float* __restrict__ bias,
                    const __half* __restrict__ resh, const float* __restrict__ pos,
                    __half* __restrict__ Ch, int K, int ldc)
{
#if defined(__CUDA_ARCH_SPECIFIC__) && (__CUDA_ARCH__ >= 1000)
    extern __shared__ char smem[];
    const uint32_t sb = smem_u32(smem);
    const int tid = threadIdx.x, lane = tid & 31, wid = tid >> 5;
    const int bm = blockIdx.y * 128, bn = blockIdx.x * 256;

    if (wid == 0) {
        asm volatile("tcgen05.alloc.cta_group::1.sync.aligned.shared::cta.b32 [%0], %1;"
                     :: "r"(sb), "r"(256u) : "memory");
        asm volatile("tcgen05.relinquish_alloc_permit.cta_group::1.sync.aligned;");
    }
    if (tid == 0) {
        #pragma unroll
        for (int s = 0; s < 4; s++)
            asm volatile("mbarrier.init.shared.b64 [%0], %1;"
                         :: "r"(sb + 8 + 8 * s), "r"(1u) : "memory");
    }
    __syncthreads();
    uint32_t tmem;
    asm volatile("ld.shared.b32 %0, [%1];" : "=r"(tmem) : "r"(sb));

    // SW64 loader: granule g of row r stored at r*64 + (g ^ ((r>>1)&3))*16
    uint32_t aDst[2]; const __half* aSrc[2];
    #pragma unroll
    for (int i = 0; i < 2; i++) {
        int idx = tid + i * 256;
        int r = idx >> 2, g = idx & 3;
        aDst[i] = sb + TC_A_OFF + (uint32_t)r * 64 + (uint32_t)((g ^ ((r >> 1) & 3)) * 16);
        aSrc[i] = A + (size_t)(bm + r) * K + g * 8;
    }
    uint32_t bDst[4]; const __half* bSrc[4];
    #pragma unroll
    for (int i = 0; i < 4; i++) {
        int idx = tid + i * 256;
        int r = idx >> 2, g = idx & 3;
        bDst[i] = sb + TC_B_OFF + (uint32_t)r * 64 + (uint32_t)((g ^ ((r >> 1) & 3)) * 16);
        bSrc[i] = Bt + (size_t)(bn + r) * K + g * 8;
    }

    const int nk = K / 32;
    const uint32_t idesc = (1u << 4) | ((256u / 8u) << 17) | ((128u / 16u) << 24);
    // SW64 K-major descriptor: layout=4, version=1, SBO=32, LBO=1
    const uint64_t DESC_BASE =
        (uint64_t(4) << 61) | (uint64_t(1) << 46) | (uint64_t(32) << 32) | (uint64_t(1) << 16);

    // prologue: fill chunks 0..2 (stages 0..2)
    #pragma unroll
    for (int st = 0; st < 3; st++) {
        if (st < nk) {
            const int k0 = st * 32;
            #pragma unroll
            for (int i = 0; i < 2; i++)
                cp_async16(aDst[i] + st * TC_ASTG, aSrc[i] + k0);
            #pragma unroll
            for (int i = 0; i < 4; i++)
                cp_async16(bDst[i] + st * TC_BSTG, bSrc[i] + k0);
            CP_COMMIT();
        }
    }

    for (int it = 0; it < nk; it++) {
        const int buf = it & 3;
        const int rem = nk - 1 - it;
        if (rem >= 2)      { CP_WAIT(2); }
        else if (rem == 1) { CP_WAIT(1); }
        else               { CP_WAIT(0); }
        __syncthreads();   // stage `buf` (chunk it) fully resident

        // 2 MMA dispatches (K16 each) for chunk it; commit to mbar[buf]
        if (wid == 0) {
            uint32_t pr;
            asm volatile("{\n\t.reg .pred p;\n\telect.sync _|p, 0xFFFFFFFF;\n\t"
                         "selp.b32 %0, 1, 0, p;\n\t}" : "=r"(pr));
            if (pr) {
                uint64_t ad = DESC_BASE | (((uint64_t)((sb + TC_A_OFF + buf * TC_ASTG) >> 4)) & 0x3FFF);
                uint64_t bd = DESC_BASE | (((uint64_t)((sb + TC_B_OFF + buf * TC_BSTG) >> 4)) & 0x3FFF);
                #pragma unroll
                for (int s = 0; s < 2; s++) {
                    uint32_t en = ((it > 0) || (s > 0)) ? 1u : 0u;
                    asm volatile("{\n\t.reg .pred p;\n\tsetp.ne.u32 p, %5, 0;\n\t"
                        "tcgen05.mma.cta_group::1.kind::f16 [%0], %1, %2, %3, {%4, %4, %4, %4}, p;\n\t}"
                        :: "r"(tmem), "l"(ad + 2 * s), "l"(bd + 2 * s), "r"(idesc),
                           "r"(0u), "r"(en) : "memory");
                }
                asm volatile(
                    "tcgen05.commit.cta_group::1.mbarrier::arrive::one.shared::cluster.b64 [%0];"
                    :: "r"(sb + 8 + (uint32_t)buf * 8) : "memory");
            }
        }

        // refill stage for chunk it+3 (previous user: chunk it-1, committed last iter)
        if (it + 3 < nk) {
            const int s2 = (it + 3) & 3;
            if (it >= 1) {
                const int cprev = it - 1;
                const uint32_t par = ((uint32_t)cprev >> 2) & 1u;
                MBAR_WAIT(sb + 8 + (uint32_t)s2 * 8, par);
            }
            const int k0 = (it + 3) * 32;
            #pragma unroll
            for (int i = 0; i < 2; i++)
                cp_async16(aDst[i] + s2 * TC_ASTG, aSrc[i] + k0);
            #pragma unroll
            for (int i = 0; i < 4; i++)
                cp_async16(bDst[i] + s2 * TC_BSTG, bSrc[i] + k0);
            CP_COMMIT();
        }
    }

    // final wait: commit of chunk nk-1 (serial MMA queue covers all prior)
    {
        const int cl = nk - 1;
        const uint32_t par = ((uint32_t)cl >> 2) & 1u;
        MBAR_WAIT(sb + 8 + (uint32_t)(cl & 3) * 8, par);
    }
    asm volatile("tcgen05.fence::after_thread_sync;" ::: "memory");

    // epilogue: warp w -> rows (w&3)*32+lane, cols (w>>2)*128 + c*32
    const int sub = wid & 3, half = wid >> 2;
    const int rg = bm + sub * 32 + lane;
    #pragma unroll
    for (int c = 0; c < 4; c++) {
        const int c0 = half * 128 + c * 32;
        uint32_t dr[32];
        asm volatile("tcgen05.ld.sync.aligned.32x32b.x32.b32 "
            "{%0, %1, %2, %3, %4, %5, %6, %7, %8, %9, %10, %11, %12, %13, %14, %15, "
            " %16, %17, %18, %19, %20, %21, %22, %23, %24, %25, %26, %27, %28, %29, %30, %31}, [%32];"
            : "=r"(dr[0]),  "=r"(dr[1]),  "=r"(dr[2]),  "=r"(dr[3]),
              "=r"(dr[4]),  "=r"(dr[5]),  "=r"(dr[6]),  "=r"(dr[7]),
              "=r"(dr[8]),  "=r"(dr[9]),  "=r"(dr[10]), "=r"(dr[11]),
              "=r"(dr[12]), "=r"(dr[13]), "=r"(dr[14]), "=r"(dr[15]),
              "=r"(dr[16]), "=r"(dr[17]), "=r"(dr[18]), "=r"(dr[19]),
              "=r"(dr[20]), "=r"(dr[21]), "=r"(dr[22]), "=r"(dr[23]),
              "=r"(dr[24]), "=r"(dr[25]), "=r"(dr[26]), "=r"(dr[27]),
              "=r"(dr[28]), "=r"(dr[29]), "=r"(dr[30]), "=r"(dr[31])
            : "r"(tmem + c0));
        asm volatile("tcgen05.wait::ld.sync.aligned;" ::: "memory");

        const int cb = bn + c0;
        const size_t rowoff = (size_t)rg * ldc + cb;
        float v[32];
        #pragma unroll
        for (int q = 0; q < 8; q++) {
            float4 b4 = *(const float4*)&bias[cb + q * 4];
            v[q*4+0] = __uint_as_float(dr[q*4+0]) + b4.x;
            v[q*4+1] = __uint_as_float(dr[q*4+1]) + b4.y;
            v[q*4+2] = __uint_as_float(dr[q*4+2]) + b4.z;
            v[q*4+3] = __uint_as_float(dr[q*4+3]) + b4.w;
        }
        if (resh) {
            #pragma unroll
            for (int q = 0; q < 4; q++) {
                uint4 rh = *(const uint4*)&resh[rowoff + q * 8];
                const __half2* hp = (const __half2*)&rh;
                #pragma unroll
                for (int e = 0; e < 4; e++) {
                    float2 f = __half22float2(hp[e]);
                    v[q * 8 + e * 2]     += f.x;
                    v[q * 8 + e * 2 + 1] += f.y;
                }
            }
        }
        if (pos) {
            const float* pp = pos + (size_t)(rg & 63) * ND + cb;
            #pragma unroll
            for (int j = 0; j < 32; j += 4) {
                float4 p4 = *(const float4*)&pp[j];
                v[j] += p4.x; v[j+1] += p4.y; v[j+2] += p4.z; v[j+3] += p4.w;
            }
        }
        #pragma unroll
        for (int q = 0; q < 4; q++) {
            __half2 h[4];
            #pragma unroll
            for (int e = 0; e < 4; e++)
                h[e] = __floats2half2_rn(v[q * 8 + e * 2], v[q * 8 + e * 2 + 1]);
            *(uint4*)&Ch[rowoff + q * 8] = *(uint4*)h;
        }
    }

    asm volatile("tcgen05.fence::before_thread_sync;" ::: "memory");
    __syncthreads();
    if (tid == 0) {
        #pragma unroll
        for (int s = 0; s < 4; s++)
            asm volatile("mbarrier.inval.shared.b64 [%0];" :: "r"(sb + 8 + 8 * s) : "memory");
    }
    __syncthreads();
    if (wid == 0) {
        asm volatile("tcgen05.dealloc.cta_group::1.sync.aligned.b32 %0, %1;" :: "r"(tmem), "r"(256u));
    }
#endif
}

// ---------------- attention: fp16 MMA flash kernel, one (b,h) per block -------
#define TPITCH 36

__global__ __launch_bounds__(128)
void attn_kernel(const float* __restrict__ rel_bias)
{
    __shared__ uint32_t qs[64 * TPITCH];
    __shared__ uint32_t ks[64 * TPITCH];
    __shared__ uint32_t vs[64 * TPITCH];

    const int h = blockIdx.x, b = blockIdx.y;
    const int tid = threadIdx.x;
    const int lane = tid & 31, w = tid >> 5;
    const int g = lane >> 2, t = lane & 3;

    const __half* qbase = g_qkvh + (size_t)b * SEQ * (3 * ND) + h * 64;

    __half* vsH = (__half*)vs;
    for (int idx = tid; idx < 512; idx += 128) {
        int s = idx >> 3, dg = idx & 7;
        const size_t r = (size_t)s * (3 * ND) + dg * 8;
        uint4 vq = *(const uint4*)(qbase + r);
        uint4 vk = *(const uint4*)(qbase + r + ND);
        *(uint4*)&qs[s * TPITCH + dg * 4] = vq;
        *(uint4*)&ks[s * TPITCH + dg * 4] = vk;
        uint4 vv = *(const uint4*)(qbase + r + 2 * ND);
        __half hv[8];
        *(uint4*)hv = vv;
        #pragma unroll
        for (int q = 0; q < 8; q++)
            vsH[(dg * 8 + q) * (TPITCH * 2) + s] = hv[q];
    }
    __syncthreads();

    float sc[8][4];
    #pragma unroll
    for (int j = 0; j < 8; j++)
        #pragma unroll
        for (int r = 0; r < 4; r++) sc[j][r] = 0.f;

    const int arow0 = (w * 16 + g) * TPITCH;
    const int arow1 = (w * 16 + g + 8) * TPITCH;
    #pragma unroll
    for (int kt = 0; kt < 4; kt++) {
        uint32_t a[4];
        a[0] = qs[arow0 + kt * 8 + t];
        a[1] = qs[arow1 + kt * 8 + t];
        a[2] = qs[arow0 + kt * 8 + t + 4];
        a[3] = qs[arow1 + kt * 8 + t + 4];
        #pragma unroll
        for (int j = 0; j < 8; j++) {
            uint32_t bf[2];
            int br = (j * 8 + g) * TPITCH + kt * 8 + t;
            bf[0] = ks[br];
            bf[1] = ks[br + 4];
            mma_f16(sc[j], a, bf);
        }
    }

    const float* rb = rel_bias + (size_t)h * 4096 + (size_t)(w * 16 + g) * 64;
    #pragma unroll
    for (int j = 0; j < 8; j++) {
        float2 b0 = *(const float2*)&rb[j * 8 + 2 * t];
        float2 b1 = *(const float2*)&rb[8 * 64 + j * 8 + 2 * t];
        sc[j][0] = sc[j][0] * 0.125f + b0.x;
        sc[j][1] = sc[j][1] * 0.125f + b0.y;
        sc[j][2] = sc[j][2] * 0.125f + b1.x;
        sc[j][3] = sc[j][3] * 0.125f + b1.y;
    }

    float m0 = -1e30f, m1 = -1e30f;
    #pragma unroll
    for (int j = 0; j < 8; j++) {
        m0 = fmaxf(m0, fmaxf(sc[j][0], sc[j][1]));
        m1 = fmaxf(m1, fmaxf(sc[j][2], sc[j][3]));
    }
    m0 = fmaxf(m0, __shfl_xor_sync(0xffffffffu, m0, 1));
    m0 = fmaxf(m0, __shfl_xor_sync(0xffffffffu, m0, 2));
    m1 = fmaxf(m1, __shfl_xor_sync(0xffffffffu, m1, 1));
    m1 = fmaxf(m1, __shfl_xor_sync(0xffffffffu, m1, 2));
    float s0 = 0.f, s1 = 0.f;
    #pragma unroll
    for (int j = 0; j < 8; j++) {
        sc[j][0] = __expf(sc[j][0] - m0); s0 += sc[j][0];
        sc[j][1] = __expf(sc[j][1] - m0); s0 += sc[j][1];
        sc[j][2] = __expf(sc[j][2] - m1); s1 += sc[j][2];
        sc[j][3] = __expf(sc[j][3] - m1); s1 += sc[j][3];
    }
    s0 += __shfl_xor_sync(0xffffffffu, s0, 1);
    s0 += __shfl_xor_sync(0xffffffffu, s0, 2);
    s1 += __shfl_xor_sync(0xffffffffu, s1, 1);
    s1 += __shfl_xor_sync(0xffffffffu, s1, 2);
    const float inv0 = 1.f / s0, inv1 = 1.f / s1;

    uint32_t pa[4][4];
    #pragma unroll
    for (int kt = 0; kt < 4; kt++) {
        pa[kt][0] = h2_as_u32(__floats2half2_rn(sc[2*kt][0]   * inv0, sc[2*kt][1]   * inv0));
        pa[kt][1] = h2_as_u32(__floats2half2_rn(sc[2*kt][2]   * inv1, sc[2*kt][3]   * inv1));
        pa[kt][2] = h2_as_u32(__floats2half2_rn(sc[2*kt+1][0] * inv0, sc[2*kt+1][1] * inv0));
        pa[kt][3] = h2_as_u32(__floats2half2_rn(sc[2*kt+1][2] * inv1, sc[2*kt+1][3] * inv1));
    }

    float oc[8][4];
    #pragma unroll
    for (int j = 0; j < 8; j++)
        #pragma unroll
        for (int r = 0; r < 4; r++) oc[j][r] = 0.f;

    #pragma unroll
    for (int kt = 0; kt < 4; kt++) {
        #pragma unroll
        for (int j = 0; j < 8; j++) {
            uint32_t bf[2];
            int br = (j * 8 + g) * TPITCH + kt * 8 + t;
            bf[0] = vs[br];
            bf[1] = vs[br + 4];
            mma_f16(oc[j], pa[kt], bf);
        }
    }

    __half* ob0 = g_o + (size_t)(b * SEQ + w * 16 + g) * ND + h * 64;
    __half* ob1 = ob0 + (size_t)8 * ND;
    #pragma unroll
    for (int j = 0; j < 8; j++) {
        *(__half2*)&ob0[j * 8 + 2 * t] = __floats2half2_rn(oc[j][0], oc[j][1]);
        *(__half2*)&ob1[j * 8 + 2 * t] = __floats2half2_rn(oc[j][2], oc[j][3]);
    }
}

// ---------------- LayerNorm: warp-per-row (fp16 in, fp32 out) -----------------
__global__ __launch_bounds__(256)
void ln_kernel(const float* __restrict__ gamma, const float* __restrict__ beta,
               float* __restrict__ out)
{
    const int wid = threadIdx.x >> 5, lane = threadIdx.x & 31;
    const size_t row = ((size_t)blockIdx.x * 8 + wid) * ND;
    const int base = lane * 32;

    float v[32];
    #pragma unroll
    for (int q = 0; q < 4; q++) {
        uint4 raw = *(const uint4*)&g_yh[row + base + q * 8];
        const __half2* hp = (const __half2*)&raw;
        #pragma unroll
        for (int e = 0; e < 4; e++) {
            float2 f = __half22float2(hp[e]);
            v[q * 8 + e * 2]     = f.x;
            v[q * 8 + e * 2 + 1] = f.y;
        }
    }

    float s = 0.f;
    #pragma unroll
    for (int j = 0; j < 32; j++) s += v[j];
    #pragma unroll
    for (int o = 16; o > 0; o >>= 1) s += __shfl_xor_sync(0xffffffffu, s, o);
    const float mu = s * (1.f / ND);

    float sq = 0.f;
    #pragma unroll
    for (int j = 0; j < 32; j++) { v[j] -= mu; sq += v[j] * v[j]; }
    #pragma unroll
    for (int o = 16; o > 0; o >>= 1) sq += __shfl_xor_sync(0xffffffffu, sq, o);
    const float inv = rsqrtf(sq * (1.f / ND) + 1e-5f);

    #pragma unroll
    for (int q = 0; q < 8; q++) {
        float4 g4 = *(const float4*)&gamma[base + q * 4];
        float4 b4 = *(const float4*)&beta[base + q * 4];
        float4 o4;
        o4.x = v[q*4+0] * inv * g4.x + b4.x;
        o4.y = v[q*4+1] * inv * g4.y + b4.y;
        o4.z = v[q*4+2] * inv * g4.z + b4.z;
        o4.w = v[q*4+3] * inv * g4.w + b4.w;
        *(float4*)&out[row + base + q * 4] = o4;
    }
}

// ---------------- launch -------------------------------------------------------
extern "C" void kernel_launch(void* const* d_in, const int* in_sizes, int n_in,
                              void* d_out, int out_size)
{
    const float* board = (const float*)d_in[0];
    const float* embW  = (const float*)d_in[1];
    const float* embB  = (const float*)d_in[2];
    const float* pos   = (const float*)d_in[3];
    const float* Wq    = (const float*)d_in[4];
    const float* bq    = (const float*)d_in[5];
    const float* Wk    = (const float*)d_in[6];
    const float* bk    = (const float*)d_in[7];
    const float* Wv    = (const float*)d_in[8];
    const float* bv    = (const float*)d_in[9];
    const float* Wo    = (const float*)d_in[10];
    const float* bo    = (const float*)d_in[11];
    const float* relb  = (const float*)d_in[12];
    const float* lng   = (const float*)d_in[13];
    const float* lnb   = (const float*)d_in[14];
    float* out = (float*)d_out;

    __half *xin, *wt, *xh, *qkvh, *o, *yh;
    float *bqkv;
    cudaGetSymbolAddress((void**)&xin,  g_xin);
    cudaGetSymbolAddress((void**)&wt,   g_Wt);
    cudaGetSymbolAddress((void**)&bqkv, g_bqkv);
    cudaGetSymbolAddress((void**)&xh,   g_xh);
    cudaGetSymbolAddress((void**)&qkvh, g_qkvh);
    cudaGetSymbolAddress((void**)&o,    g_o);
    cudaGetSymbolAddress((void**)&yh,   g_yh);

    cudaFuncSetAttribute(gemm_mma_kernel,
                         cudaFuncAttributeMaxDynamicSharedMemorySize, GSMEM);
    cudaFuncSetAttribute(gemm_tc_kernel,
                         cudaFuncAttributeMaxDynamicSharedMemorySize, TC_SMEM);

    // Runtime dispatch: tcgen05 body exists only in the sm_103a cubin.
    cudaFuncAttributes fa{};
    cudaFuncGetAttributes(&fa, gemm_tc_kernel);
    const bool use_tc = (fa.numRegs >= 32);

    board_transpose_kernel<<<NB, 256>>>(board);
    concat_bias_kernel<<<(3 * ND + 255) / 256, 256>>>(bq, bk, bv);

    dim3 tb(32, 8);

    transpose_kernel<<<dim3(ND / 32, KPAD / 32), tb>>>(embW, wt, NC, ND, KPAD);
    if (use_tc)
        gemm_tc_kernel<<<dim3(ND / 256, MR / 128), 256, TC_SMEM>>>(
            xin, wt, embB, nullptr, pos, xh, KPAD, ND);
    else
        gemm_mma_kernel<<<dim3(ND / 128, MR / 128), 256, GSMEM>>>(
            xin, wt, embB, nullptr, pos, xh, KPAD, ND);

    transpose_kernel<<<dim3(ND / 32, ND / 32), tb>>>(Wq, wt,                 ND, ND, ND);
    transpose_kernel<<<dim3(ND / 32, ND / 32), tb>>>(Wk, wt + (size_t)ND*ND,   ND, ND, ND);
    transpose_kernel<<<dim3(ND / 32, ND / 32), tb>>>(Wv, wt + (size_t)2*ND*ND, ND, ND, ND);
    if (use_tc)
        gemm_tc_kernel<<<dim3(3 * ND / 256, MR / 128), 256, TC_SMEM>>>(
            xh, wt, bqkv, nullptr, nullptr, qkvh, ND, 3 * ND);
    else
        gemm_mma_kernel<<<dim3(3 * ND / 128, MR / 128), 256, GSMEM>>>(
            xh, wt, bqkv, nullptr, nullptr, qkvh, ND, 3 * ND);

    attn_kernel<<<dim3(NH, NB), 128>>>(relb);

    transpose_kernel<<<dim3(ND / 32, ND / 32), tb>>>(Wo, wt, ND, ND, ND);
    if (use_tc)
        gemm_tc_kernel<<<dim3(ND / 256, MR / 128), 256, TC_SMEM>>>(
            o, wt, bo, xh, nullptr, yh, ND, ND);
    else
        gemm_mma_kernel<<<dim3(ND / 128, MR / 128), 256, GSMEM>>>(
            o, wt, bo, xh, nullptr, yh, ND, ND);

    ln_kernel<<<MR / 8, 256>>>(lng, lnb, out);
}